// round 13
// baseline (speedup 1.0000x reference)
#include <cuda_runtime.h>
#include <cuda_bf16.h>
#include <math_constants.h>
#include <cstdint>

#define BB  16
#define SS  1024
#define DD  1024
#define HH  16
#define DKK 64
#define MM  (BB*SS)          // 16384
#define QSZ (BB*HH*SS*DKK)   // 16M elems

// ---------------- scratch (__device__ globals; no runtime allocs) ----------
__device__ __nv_bfloat16 g_Ah[MM*DD];       // hi of X
__device__ __nv_bfloat16 g_Al[MM*DD];       // lo of X
__device__ __nv_bfloat16 g_Oh[MM*DD];       // hi of attention output
__device__ __nv_bfloat16 g_Ol[MM*DD];       // lo of attention output
__device__ __nv_bfloat16 g_Wh[4][DD*DD];    // transposed weights, hi
__device__ __nv_bfloat16 g_Wl[4][DD*DD];    // transposed weights, lo
__device__ __nv_bfloat16 g_QKVh[3][QSZ];    // Q,K,V hi  [B,H,S,DK]
__device__ __nv_bfloat16 g_QKVl[3][QSZ];    // Q,K,V lo

// ---------------- PTX helpers (sm_80-era only: valid in base sm_103 PTX) ---
__device__ __forceinline__ uint32_t cvta_s(const void* p) {
    return (uint32_t)__cvta_generic_to_shared(p);
}
#define CP_ASYNC16(saddr, gptr) \
    asm volatile("cp.async.cg.shared.global [%0], [%1], 16;" \
                 :: "r"((uint32_t)(saddr)), "l"(gptr))
#define CP_ASYNC_COMMIT() asm volatile("cp.async.commit_group;" ::: "memory")
#define CP_ASYNC_WAIT(n)  asm volatile("cp.async.wait_group %0;" :: "n"(n) : "memory")

#define LDMATRIX_X4(r0, r1, r2, r3, addr) \
    asm volatile("ldmatrix.sync.aligned.m8n8.x4.shared.b16 {%0,%1,%2,%3}, [%4];" \
                 : "=r"(r0), "=r"(r1), "=r"(r2), "=r"(r3) : "r"(addr))
#define LDMATRIX_X4T(r0, r1, r2, r3, addr) \
    asm volatile("ldmatrix.sync.aligned.m8n8.x4.trans.shared.b16 {%0,%1,%2,%3}, [%4];" \
                 : "=r"(r0), "=r"(r1), "=r"(r2), "=r"(r3) : "r"(addr))
#define LDMATRIX_X2(r0, r1, addr) \
    asm volatile("ldmatrix.sync.aligned.m8n8.x2.shared.b16 {%0,%1}, [%2];" \
                 : "=r"(r0), "=r"(r1) : "r"(addr))

__device__ __forceinline__ void mma_bf16(float* d, const uint32_t* a, uint32_t b0, uint32_t b1) {
    asm volatile("mma.sync.aligned.m16n8k16.row.col.f32.bf16.bf16.f32 "
        "{%0,%1,%2,%3}, {%4,%5,%6,%7}, {%8,%9}, {%0,%1,%2,%3};"
        : "+f"(d[0]), "+f"(d[1]), "+f"(d[2]), "+f"(d[3])
        : "r"(a[0]), "r"(a[1]), "r"(a[2]), "r"(a[3]), "r"(b0), "r"(b1));
}

__device__ __forceinline__ uint32_t pack2bf(float x, float y) {
    __nv_bfloat162 t = __floats2bfloat162_rn(x, y);
    return *reinterpret_cast<uint32_t*>(&t);
}
__device__ __forceinline__ void split2(float x, float y, uint32_t& hi, uint32_t& lo) {
    __nv_bfloat16 hx = __float2bfloat16(x), hy = __float2bfloat16(y);
    float rx = x - __bfloat162float(hx);
    float ry = y - __bfloat162float(hy);
    __nv_bfloat162 h2; h2.x = hx; h2.y = hy;
    hi = *reinterpret_cast<uint32_t*>(&h2);
    lo = pack2bf(rx, ry);
}

// ---------------- fp32 -> bf16 hi/lo split ---------------------------------
__global__ __launch_bounds__(256)
void convert_hl_kernel(const float* __restrict__ X,
                       __nv_bfloat16* __restrict__ H, __nv_bfloat16* __restrict__ L)
{
    const size_t i = ((size_t)blockIdx.x * 256 + threadIdx.x) * 4;
    float4 v = *(const float4*)(X + i);
    float f[4] = {v.x, v.y, v.z, v.w};
    ushort4 hv, lv;
    unsigned short* hp = &hv.x; unsigned short* lp = &lv.x;
    #pragma unroll
    for (int j = 0; j < 4; j++) {
        __nv_bfloat16 h = __float2bfloat16(f[j]);
        float r = f[j] - __bfloat162float(h);
        hp[j] = __bfloat16_as_ushort(h);
        lp[j] = __bfloat16_as_ushort(__float2bfloat16(r));
    }
    *(ushort4*)(H + i) = hv;
    *(ushort4*)(L + i) = lv;
}

// ---------------- W [K,N] -> W^T [N,K], split hi/lo ------------------------
__global__ __launch_bounds__(256)
void convert_wt_kernel(const float* __restrict__ W,
                       __nv_bfloat16* __restrict__ Th, __nv_bfloat16* __restrict__ Tl)
{
    __shared__ float tile[32][33];
    const int n0 = blockIdx.x * 32, k0 = blockIdx.y * 32;
    const int tx = threadIdx.x, ty = threadIdx.y;  // 32 x 8
    #pragma unroll
    for (int i = 0; i < 32; i += 8)
        tile[ty + i][tx] = W[(size_t)(k0 + ty + i) * DD + n0 + tx];
    __syncthreads();
    #pragma unroll
    for (int i = 0; i < 32; i += 8) {
        float v = tile[tx][ty + i];
        __nv_bfloat16 h = __float2bfloat16(v);
        float r = v - __bfloat162float(h);
        size_t o = (size_t)(n0 + ty + i) * DD + k0 + tx;
        Th[o] = h;
        Tl[o] = __float2bfloat16(r);
    }
}

// ---------------------------------------------------------------------------
// Tensor-core GEMM via mma.sync (bf16 hi/lo, 3 products -> ~fp32 accuracy).
// CTA 128x128, warps 2(M)x4(N) of 64x32.  R12: KCH=32, TWO-stage ring,
// 80KB smem/CTA + launch_bounds(256,2) -> 2 CTAs RESIDENT PER SM so one CTA's
// HMMAs cover the other's barrier/wait dead time (R9-R11 showed 43% tensor
// idle with nothing saturated at 1 CTA/SM). One __syncthreads per chunk;
// load(c+1) issued post-sync into the stage freed by compute(c-1).
// MODE 0: fp32 C.  MODE 1: permuted bf16 hi/lo out (blockIdx.z picks W / dst).
// ---------------------------------------------------------------------------
#define KCH    32
#define TSTR   40                        // smem row stride (80 B, conflict-free)
#define TILE_B (128 * TSTR * 2)          // 10240 bytes
#define STAGE_B (4 * TILE_B)             // 40960 bytes
#define GSTAGES 2
#define GSMEM  (GSTAGES * STAGE_B)       // 81920 bytes

template<int MODE>
__global__ __launch_bounds__(256, 2)
void mma_gemm_kernel(const __nv_bfloat16* __restrict__ Ah, const __nv_bfloat16* __restrict__ Al,
                     const __nv_bfloat16* __restrict__ Bh0, const __nv_bfloat16* __restrict__ Bl0,
                     float* __restrict__ C,
                     __nv_bfloat16* __restrict__ Ch0, __nv_bfloat16* __restrict__ Cl0)
{
    constexpr int Kdim = DD, Ndim = DD;
    extern __shared__ char smem_raw[];
    const uint32_t sbase = cvta_s(smem_raw);

    const int z = blockIdx.z;
    const __nv_bfloat16* Bh = Bh0 + (size_t)z * DD * DD;
    const __nv_bfloat16* Bl = Bl0 + (size_t)z * DD * DD;
    __nv_bfloat16* Ch = (MODE == 1) ? Ch0 + (size_t)z * QSZ : nullptr;
    __nv_bfloat16* Cl = (MODE == 1) ? Cl0 + (size_t)z * QSZ : nullptr;

    const int tid  = threadIdx.x;
    const int wid  = tid >> 5, lane = tid & 31;
    const int wm   = wid & 1;
    const int wn   = wid >> 1;
    const int m0   = blockIdx.y * 128, n0 = blockIdx.x * 128;

    float acc[4][4][4] = {};

    // chunk = [128 rows x 32 bf16] x 4 tiles = 512 16B-lines/tile, 8/thread.
    auto load_chunk = [&](int c, int stage) {
        const uint32_t so = sbase + stage * STAGE_B;
        const int k0 = c * KCH;
        #pragma unroll
        for (int u = 0; u < 2; u++) {
            const int id  = tid + u * 256;       // 0..511
            const int row = id >> 2, cl = id & 3;
            const uint32_t sw = row * (TSTR * 2) + cl * 16;
            const size_t ga = (size_t)(m0 + row) * Kdim + k0 + cl * 8;
            const size_t gb = (size_t)(n0 + row) * Kdim + k0 + cl * 8;
            CP_ASYNC16(so + sw,              Ah + ga);
            CP_ASYNC16(so + TILE_B + sw,     Al + ga);
            CP_ASYNC16(so + 2 * TILE_B + sw, Bh + gb);
            CP_ASYNC16(so + 3 * TILE_B + sw, Bl + gb);
        }
        CP_ASYNC_COMMIT();
    };

    const uint32_t a_row = wm * 64 + (lane & 15);
    const uint32_t a_sub = (lane >> 4) * 16;
    const uint32_t b_row = wn * 32 + (lane & 7);
    const uint32_t b_sub = ((lane >> 3) & 1) * 16;

    auto compute = [&](int stage) {
        const uint32_t so = sbase + stage * STAGE_B;
        #pragma unroll
        for (int ks = 0; ks < 2; ks++) {
            uint32_t ah[4][4], al[4][4], bh[4][2], bl[4][2];
            #pragma unroll
            for (int i = 0; i < 4; i++) {
                const uint32_t off = (a_row + i * 16) * (TSTR * 2) + ks * 32 + a_sub;
                LDMATRIX_X4(ah[i][0], ah[i][1], ah[i][2], ah[i][3], so + off);
                LDMATRIX_X4(al[i][0], al[i][1], al[i][2], al[i][3], so + TILE_B + off);
            }
            #pragma unroll
            for (int j = 0; j < 4; j++) {
                const uint32_t off = (b_row + j * 8) * (TSTR * 2) + ks * 32 + b_sub;
                LDMATRIX_X2(bh[j][0], bh[j][1], so + 2 * TILE_B + off);
                LDMATRIX_X2(bl[j][0], bl[j][1], so + 3 * TILE_B + off);
            }
            #pragma unroll
            for (int i = 0; i < 4; i++)
                #pragma unroll
                for (int j = 0; j < 4; j++)
                    mma_bf16(acc[i][j], ah[i], bh[j][0], bh[j][1]);
            #pragma unroll
            for (int i = 0; i < 4; i++)
                #pragma unroll
                for (int j = 0; j < 4; j++)
                    mma_bf16(acc[i][j], ah[i], bl[j][0], bl[j][1]);
            #pragma unroll
            for (int i = 0; i < 4; i++)
                #pragma unroll
                for (int j = 0; j < 4; j++)
                    mma_bf16(acc[i][j], al[i], bh[j][0], bh[j][1]);
        }
    };

    const int NCHUNK = Kdim / KCH;       // 32
    load_chunk(0, 0);
    #pragma unroll 1
    for (int c = 0; c < NCHUNK; c++) {
        CP_ASYNC_WAIT(0);                // chunk c delivered
        __syncthreads();                 // compute(c-1) finished -> stage (c+1)&1 free
        if (c + 1 < NCHUNK) load_chunk(c + 1, (c + 1) & 1);   // overlaps compute(c)
        compute(c & 1);
    }

    #pragma unroll
    for (int i = 0; i < 4; i++) {
        #pragma unroll
        for (int j = 0; j < 4; j++) {
            const int col = n0 + wn * 32 + j * 8 + 2 * (lane & 3);
            #pragma unroll
            for (int hlf = 0; hlf < 2; hlf++) {
                const int row = m0 + wm * 64 + i * 16 + (lane >> 2) + hlf * 8;
                const float v0 = acc[i][j][hlf * 2], v1 = acc[i][j][hlf * 2 + 1];
                if (MODE == 0) {
                    float* p = C + (size_t)row * Ndim + col;
                    *(float2*)p = make_float2(v0, v1);
                } else {
                    const int b = row >> 10, s = row & 1023;
                    const int h = col >> 6, dk = col & 63;
                    const size_t off = ((size_t)(b * HH + h) * SS + s) * DKK + dk;
                    uint32_t hi, lo;
                    split2(v0, v1, hi, lo);
                    *(uint32_t*)(Ch + off) = hi;
                    *(uint32_t*)(Cl + off) = lo;
                }
            }
        }
    }
}

// ---------------------------------------------------------------------------
// Flash attention on mma.sync (bf16 hi/lo, 3 products for QK^T and PV).
// BQ=128 q-rows x (h,b); 256 threads, 8 warps over M (16 rows each).
// 3-stage KV ring of 64-key tiles, 1 sync/tile. (Unchanged from R8.)
// ---------------------------------------------------------------------------
#define FBQ     128
#define FT_B    9216                      // 64x64 bf16 tile @ 144B rows
#define FSTG_B  (4 * FT_B)                // Kh,Kl,Vh,Vl = 36864
#define FQ_B    (128 * 144)               // 18432 (128-row Q tile)
#define FQH_OFF (3 * FSTG_B)              // 110592
#define FQL_OFF (FQH_OFF + FQ_B)
#define FSMEM   (FQL_OFF + FQ_B)          // 147456

__global__ __launch_bounds__(256)
void flash_mma_kernel(const float* __restrict__ bias, const float* __restrict__ bt,
                      __nv_bfloat16* __restrict__ Oh, __nv_bfloat16* __restrict__ Ol)
{
    extern __shared__ char fsm[];
    const uint32_t sb = cvta_s(fsm);
    const int tid = threadIdx.x, wid = tid >> 5, lane = tid & 31;
    const int qb = blockIdx.x * FBQ, h = blockIdx.y, b = blockIdx.z;
    const int bh = b * HH + h;
    const float btv = bt[h];

    const __nv_bfloat16* Qhg = g_QKVh[0] + ((size_t)bh * SS + qb) * DKK;
    const __nv_bfloat16* Qlg = g_QKVl[0] + ((size_t)bh * SS + qb) * DKK;
    const __nv_bfloat16* Khg = g_QKVh[1] + (size_t)bh * SS * DKK;
    const __nv_bfloat16* Klg = g_QKVl[1] + (size_t)bh * SS * DKK;
    const __nv_bfloat16* Vhg = g_QKVh[2] + (size_t)bh * SS * DKK;
    const __nv_bfloat16* Vlg = g_QKVl[2] + (size_t)bh * SS * DKK;

    #pragma unroll
    for (int u = 0; u < 4; u++) {
        const int id = tid + u * 256;            // 0..1023
        const int row = id >> 3, c = id & 7;
        const uint32_t off = row * 144 + c * 16;
        CP_ASYNC16(sb + FQH_OFF + off, Qhg + row * 64 + c * 8);
        CP_ASYNC16(sb + FQL_OFF + off, Qlg + row * 64 + c * 8);
    }
    CP_ASYNC_COMMIT();

    auto load_kv = [&](int t, int stage) {
        const uint32_t so = sb + stage * FSTG_B;
        const size_t g0 = (size_t)(t * 64) * DKK;
        #pragma unroll
        for (int u = 0; u < 2; u++) {
            const int id = tid + u * 256;        // 0..511
            const int row = id >> 3, c = id & 7;
            const uint32_t off = row * 144 + c * 16;
            const size_t g = g0 + row * 64 + c * 8;
            CP_ASYNC16(so + off,            Khg + g);
            CP_ASYNC16(so + FT_B + off,     Klg + g);
            CP_ASYNC16(so + 2 * FT_B + off, Vhg + g);
            CP_ASYNC16(so + 3 * FT_B + off, Vlg + g);
        }
        CP_ASYNC_COMMIT();
    };

    load_kv(0, 0);
    load_kv(1, 1);
    CP_ASYNC_WAIT(2);       // Q group done
    __syncthreads();

    uint32_t qh[4][4], ql[4][4];
    {
        const uint32_t qrow = wid * 16 + (lane & 15);
        #pragma unroll
        for (int ks = 0; ks < 4; ks++) {
            const uint32_t ad = sb + FQH_OFF + qrow * 144 + ks * 32 + (lane >> 4) * 16;
            LDMATRIX_X4(qh[ks][0], qh[ks][1], qh[ks][2], qh[ks][3], ad);
            LDMATRIX_X4(ql[ks][0], ql[ks][1], ql[ks][2], ql[ks][3], ad + FQ_B);
        }
    }

    float out[8][4] = {};
    float m0 = -CUDART_INF_F, m1 = -CUDART_INF_F;
    float l0 = 0.f, l1 = 0.f;

    const int r0g = qb + wid * 16 + (lane >> 2);
    const int cb0 = 2 * (lane & 3);

    #pragma unroll 1
    for (int t = 0; t < 16; t++) {
        if (t < 15) { CP_ASYNC_WAIT(1); }
        else        { CP_ASYNC_WAIT(0); }
        __syncthreads();

        const uint32_t so = sb + (t % 3) * FSTG_B;

        float sacc[8][4];
        #pragma unroll
        for (int nb = 0; nb < 8; nb++) {
            sacc[nb][0] = sacc[nb][1] = sacc[nb][2] = sacc[nb][3] = 0.f;
            uint32_t kA[4], kB[4], lA[4], lB[4];
            const uint32_t kad = so + (nb * 8 + (lane & 7)) * 144 + (lane >> 3) * 16;
            LDMATRIX_X4(kA[0], kA[1], kA[2], kA[3], kad);
            LDMATRIX_X4(kB[0], kB[1], kB[2], kB[3], kad + 64);
            LDMATRIX_X4(lA[0], lA[1], lA[2], lA[3], kad + FT_B);
            LDMATRIX_X4(lB[0], lB[1], lB[2], lB[3], kad + FT_B + 64);
            #pragma unroll
            for (int ks = 0; ks < 4; ks++) {
                const uint32_t bh0 = (ks < 2) ? kA[2*ks]     : kB[2*(ks-2)];
                const uint32_t bh1 = (ks < 2) ? kA[2*ks + 1] : kB[2*(ks-2) + 1];
                const uint32_t bl0 = (ks < 2) ? lA[2*ks]     : lB[2*(ks-2)];
                const uint32_t bl1 = (ks < 2) ? lA[2*ks + 1] : lB[2*(ks-2) + 1];
                mma_bf16(sacc[nb], qh[ks], bh0, bh1);
                mma_bf16(sacc[nb], qh[ks], bl0, bl1);
                mma_bf16(sacc[nb], ql[ks], bh0, bh1);
            }
        }

        float tmax0 = m0, tmax1 = m1;
        #pragma unroll
        for (int nb = 0; nb < 8; nb++) {
            const int colg = t * 64 + nb * 8 + cb0;
            const float2 b0 = *(const float2*)(bias + (size_t)r0g * SS + colg);
            const float2 b1 = *(const float2*)(bias + (size_t)(r0g + 8) * SS + colg);
            sacc[nb][0] = fmaf(btv, b0.x, sacc[nb][0] * 0.125f);
            sacc[nb][1] = fmaf(btv, b0.y, sacc[nb][1] * 0.125f);
            sacc[nb][2] = fmaf(btv, b1.x, sacc[nb][2] * 0.125f);
            sacc[nb][3] = fmaf(btv, b1.y, sacc[nb][3] * 0.125f);
            tmax0 = fmaxf(tmax0, fmaxf(sacc[nb][0], sacc[nb][1]));
            tmax1 = fmaxf(tmax1, fmaxf(sacc[nb][2], sacc[nb][3]));
        }
        tmax0 = fmaxf(tmax0, __shfl_xor_sync(0xFFFFFFFF, tmax0, 1));
        tmax0 = fmaxf(tmax0, __shfl_xor_sync(0xFFFFFFFF, tmax0, 2));
        tmax1 = fmaxf(tmax1, __shfl_xor_sync(0xFFFFFFFF, tmax1, 1));
        tmax1 = fmaxf(tmax1, __shfl_xor_sync(0xFFFFFFFF, tmax1, 2));

        const float sc0 = __expf(m0 - tmax0);
        const float sc1 = __expf(m1 - tmax1);
        m0 = tmax0; m1 = tmax1;
        l0 *= sc0;  l1 *= sc1;
        #pragma unroll
        for (int nb = 0; nb < 8; nb++) {
            out[nb][0] *= sc0; out[nb][1] *= sc0;
            out[nb][2] *= sc1; out[nb][3] *= sc1;
        }

        uint32_t ph[8][2], pl[8][2];
        float rs0 = 0.f, rs1 = 0.f;
        #pragma unroll
        for (int nb = 0; nb < 8; nb++) {
            const float p0 = __expf(sacc[nb][0] - m0);
            const float p1 = __expf(sacc[nb][1] - m0);
            const float p2 = __expf(sacc[nb][2] - m1);
            const float p3 = __expf(sacc[nb][3] - m1);
            rs0 += p0 + p1; rs1 += p2 + p3;
            split2(p0, p1, ph[nb][0], pl[nb][0]);
            split2(p2, p3, ph[nb][1], pl[nb][1]);
        }
        rs0 += __shfl_xor_sync(0xFFFFFFFF, rs0, 1);
        rs0 += __shfl_xor_sync(0xFFFFFFFF, rs0, 2);
        rs1 += __shfl_xor_sync(0xFFFFFFFF, rs1, 1);
        rs1 += __shfl_xor_sync(0xFFFFFFFF, rs1, 2);
        l0 += rs0; l1 += rs1;

        #pragma unroll
        for (int nb = 0; nb < 8; nb++) {
            uint32_t vA[4], vB[4], wA[4], wB[4];
            const uint32_t vad = so + 2 * FT_B
                               + ((lane & 7) + 8 * (lane >> 3)) * 144 + nb * 16;
            LDMATRIX_X4T(vA[0], vA[1], vA[2], vA[3], vad);
            LDMATRIX_X4T(vB[0], vB[1], vB[2], vB[3], vad + 32 * 144);
            LDMATRIX_X4T(wA[0], wA[1], wA[2], wA[3], vad + FT_B);
            LDMATRIX_X4T(wB[0], wB[1], wB[2], wB[3], vad + FT_B + 32 * 144);
            #pragma unroll
            for (int ks = 0; ks < 4; ks++) {
                const uint32_t vh0 = (ks < 2) ? vA[2*ks]     : vB[2*(ks-2)];
                const uint32_t vh1 = (ks < 2) ? vA[2*ks + 1] : vB[2*(ks-2) + 1];
                const uint32_t vl0 = (ks < 2) ? wA[2*ks]     : wB[2*(ks-2)];
                const uint32_t vl1 = (ks < 2) ? wA[2*ks + 1] : wB[2*(ks-2) + 1];
                uint32_t aH[4] = { ph[2*ks][0], ph[2*ks][1], ph[2*ks+1][0], ph[2*ks+1][1] };
                uint32_t aL[4] = { pl[2*ks][0], pl[2*ks][1], pl[2*ks+1][0], pl[2*ks+1][1] };
                mma_bf16(out[nb], aH, vh0, vh1);
                mma_bf16(out[nb], aH, vl0, vl1);
                mma_bf16(out[nb], aL, vh0, vh1);
            }
        }

        if (t + 2 < 16) load_kv(t + 2, (t + 2) % 3);
    }

    const float inv0 = 1.f / l0, inv1 = 1.f / l1;
    const size_t o0 = ((size_t)b * SS + r0g) * (HH * DKK) + h * DKK;
    const size_t o1 = ((size_t)b * SS + r0g + 8) * (HH * DKK) + h * DKK;
    #pragma unroll
    for (int nb = 0; nb < 8; nb++) {
        const int dk = nb * 8 + cb0;
        uint32_t hi, lo;
        split2(out[nb][0] * inv0, out[nb][1] * inv0, hi, lo);
        *(uint32_t*)(Oh + o0 + dk) = hi;
        *(uint32_t*)(Ol + o0 + dk) = lo;
        split2(out[nb][2] * inv1, out[nb][3] * inv1, hi, lo);
        *(uint32_t*)(Oh + o1 + dk) = hi;
        *(uint32_t*)(Ol + o1 + dk) = lo;
    }
}

// ---------------- launch ---------------------------------------------------
extern "C" void kernel_launch(void* const* d_in, const int* in_sizes, int n_in,
                              void* d_out, int out_size)
{
    (void)in_sizes; (void)n_in; (void)out_size;
    const float* X    = (const float*)d_in[0];
    const float* bias = (const float*)d_in[1];
    const float* Wmat[4] = { (const float*)d_in[2], (const float*)d_in[3],
                             (const float*)d_in[4], (const float*)d_in[5] };
    const float* bt = (const float*)d_in[6];
    float* out = (float*)d_out;

    __nv_bfloat16 *Ahp, *Alp, *Ohp, *Olp, *Whp, *Wlp, *QKVh, *QKVl;
    cudaGetSymbolAddress((void**)&Ahp,  g_Ah);
    cudaGetSymbolAddress((void**)&Alp,  g_Al);
    cudaGetSymbolAddress((void**)&Ohp,  g_Oh);
    cudaGetSymbolAddress((void**)&Olp,  g_Ol);
    cudaGetSymbolAddress((void**)&Whp,  g_Wh);
    cudaGetSymbolAddress((void**)&Wlp,  g_Wl);
    cudaGetSymbolAddress((void**)&QKVh, g_QKVh);
    cudaGetSymbolAddress((void**)&QKVl, g_QKVl);

    cudaFuncSetAttribute(mma_gemm_kernel<0>,
                         cudaFuncAttributeMaxDynamicSharedMemorySize, GSMEM);
    cudaFuncSetAttribute(mma_gemm_kernel<1>,
                         cudaFuncAttributeMaxDynamicSharedMemorySize, GSMEM);
    cudaFuncSetAttribute(flash_mma_kernel,
                         cudaFuncAttributeMaxDynamicSharedMemorySize, FSMEM);

    convert_hl_kernel<<<(MM * DD) / 1024, 256>>>(X, Ahp, Alp);
    for (int w = 0; w < 4; w++)
        convert_wt_kernel<<<dim3(32, 32), dim3(32, 8)>>>(
            Wmat[w], Whp + (size_t)w * DD * DD, Wlp + (size_t)w * DD * DD);

    // fused Q/K/V projections: grid.z picks weight + destination
    dim3 qkv_grid(DD / 128, MM / 128, 3);
    mma_gemm_kernel<1><<<qkv_grid, 256, GSMEM>>>(Ahp, Alp, Whp, Wlp,
                                                 nullptr, QKVh, QKVl);

    flash_mma_kernel<<<dim3(SS / FBQ, HH, BB), 256, FSMEM>>>(bias, bt, Ohp, Olp);

    // output projection straight from bf16 hi/lo O
    dim3 ogrid(DD / 128, MM / 128, 1);
    mma_gemm_kernel<0><<<ogrid, 256, GSMEM>>>(Ohp, Olp,
        Whp + 3 * (size_t)DD * DD, Wlp + 3 * (size_t)DD * DD, out, nullptr, nullptr);
}

// round 14
// speedup vs baseline: 1.2719x; 1.2719x over previous
#include <cuda_runtime.h>
#include <cuda_bf16.h>
#include <math_constants.h>
#include <cstdint>

#define BB  16
#define SS  1024
#define DD  1024
#define HH  16
#define DKK 64
#define MM  (BB*SS)          // 16384
#define QSZ (BB*HH*SS*DKK)   // 16M elems

// ---------------- scratch (__device__ globals; no runtime allocs) ----------
__device__ __nv_bfloat16 g_Ah[MM*DD];
__device__ __nv_bfloat16 g_Al[MM*DD];
__device__ __nv_bfloat16 g_Oh[MM*DD];
__device__ __nv_bfloat16 g_Ol[MM*DD];
__device__ __nv_bfloat16 g_Wh[4][DD*DD];
__device__ __nv_bfloat16 g_Wl[4][DD*DD];
__device__ __nv_bfloat16 g_QKVh[3][QSZ];
__device__ __nv_bfloat16 g_QKVl[3][QSZ];

// ---------------- PTX helpers (sm_80-era only) -----------------------------
__device__ __forceinline__ uint32_t cvta_s(const void* p) {
    return (uint32_t)__cvta_generic_to_shared(p);
}
#define CP_ASYNC16(saddr, gptr) \
    asm volatile("cp.async.cg.shared.global [%0], [%1], 16;" \
                 :: "r"((uint32_t)(saddr)), "l"(gptr))
#define CP_ASYNC_COMMIT() asm volatile("cp.async.commit_group;" ::: "memory")
#define CP_ASYNC_WAIT(n)  asm volatile("cp.async.wait_group %0;" :: "n"(n) : "memory")

#define LDMATRIX_X4(r0, r1, r2, r3, addr) \
    asm volatile("ldmatrix.sync.aligned.m8n8.x4.shared.b16 {%0,%1,%2,%3}, [%4];" \
                 : "=r"(r0), "=r"(r1), "=r"(r2), "=r"(r3) : "r"(addr))
#define LDMATRIX_X4T(r0, r1, r2, r3, addr) \
    asm volatile("ldmatrix.sync.aligned.m8n8.x4.trans.shared.b16 {%0,%1,%2,%3}, [%4];" \
                 : "=r"(r0), "=r"(r1), "=r"(r2), "=r"(r3) : "r"(addr))
#define LDMATRIX_X2(r0, r1, addr) \
    asm volatile("ldmatrix.sync.aligned.m8n8.x2.shared.b16 {%0,%1}, [%2];" \
                 : "=r"(r0), "=r"(r1) : "r"(addr))

__device__ __forceinline__ void mma_bf16(float* d, const uint32_t* a, uint32_t b0, uint32_t b1) {
    asm volatile("mma.sync.aligned.m16n8k16.row.col.f32.bf16.bf16.f32 "
        "{%0,%1,%2,%3}, {%4,%5,%6,%7}, {%8,%9}, {%0,%1,%2,%3};"
        : "+f"(d[0]), "+f"(d[1]), "+f"(d[2]), "+f"(d[3])
        : "r"(a[0]), "r"(a[1]), "r"(a[2]), "r"(a[3]), "r"(b0), "r"(b1));
}

__device__ __forceinline__ uint32_t pack2bf(float x, float y) {
    __nv_bfloat162 t = __floats2bfloat162_rn(x, y);
    return *reinterpret_cast<uint32_t*>(&t);
}
__device__ __forceinline__ void split2(float x, float y, uint32_t& hi, uint32_t& lo) {
    __nv_bfloat16 hx = __float2bfloat16(x), hy = __float2bfloat16(y);
    float rx = x - __bfloat162float(hx);
    float ry = y - __bfloat162float(hy);
    __nv_bfloat162 h2; h2.x = hx; h2.y = hy;
    hi = *reinterpret_cast<uint32_t*>(&h2);
    lo = pack2bf(rx, ry);
}

// ---------------- fp32 -> bf16 hi/lo split ---------------------------------
__global__ __launch_bounds__(256)
void convert_hl_kernel(const float* __restrict__ X,
                       __nv_bfloat16* __restrict__ H, __nv_bfloat16* __restrict__ L)
{
    const size_t i = ((size_t)blockIdx.x * 256 + threadIdx.x) * 4;
    float4 v = *(const float4*)(X + i);
    float f[4] = {v.x, v.y, v.z, v.w};
    ushort4 hv, lv;
    unsigned short* hp = &hv.x; unsigned short* lp = &lv.x;
    #pragma unroll
    for (int j = 0; j < 4; j++) {
        __nv_bfloat16 h = __float2bfloat16(f[j]);
        float r = f[j] - __bfloat162float(h);
        hp[j] = __bfloat16_as_ushort(h);
        lp[j] = __bfloat16_as_ushort(__float2bfloat16(r));
    }
    *(ushort4*)(H + i) = hv;
    *(ushort4*)(L + i) = lv;
}

// ---------------- W [K,N] -> W^T [N,K], split hi/lo ------------------------
__global__ __launch_bounds__(256)
void convert_wt_kernel(const float* __restrict__ W,
                       __nv_bfloat16* __restrict__ Th, __nv_bfloat16* __restrict__ Tl)
{
    __shared__ float tile[32][33];
    const int n0 = blockIdx.x * 32, k0 = blockIdx.y * 32;
    const int tx = threadIdx.x, ty = threadIdx.y;  // 32 x 8
    #pragma unroll
    for (int i = 0; i < 32; i += 8)
        tile[ty + i][tx] = W[(size_t)(k0 + ty + i) * DD + n0 + tx];
    __syncthreads();
    #pragma unroll
    for (int i = 0; i < 32; i += 8) {
        float v = tile[tx][ty + i];
        __nv_bfloat16 h = __float2bfloat16(v);
        float r = v - __bfloat162float(h);
        size_t o = (size_t)(n0 + ty + i) * DD + k0 + tx;
        Th[o] = h;
        Tl[o] = __float2bfloat16(r);
    }
}

// ---------------------------------------------------------------------------
// Tensor-core GEMM (R8 config — best measured; all structural variants were
// neutral, so it sits at the legacy-HMMA practical ceiling).
// ---------------------------------------------------------------------------
#define KCH    64
#define TSTR   72
#define TILE_B (128 * TSTR * 2)          // 18432
#define STAGE_B (4 * TILE_B)             // 73728
#define GSTAGES 3
#define GSMEM  (GSTAGES * STAGE_B)       // 221184

template<int MODE>
__global__ __launch_bounds__(256, 1)
void mma_gemm_kernel(const __nv_bfloat16* __restrict__ Ah, const __nv_bfloat16* __restrict__ Al,
                     const __nv_bfloat16* __restrict__ Bh0, const __nv_bfloat16* __restrict__ Bl0,
                     float* __restrict__ C,
                     __nv_bfloat16* __restrict__ Ch0, __nv_bfloat16* __restrict__ Cl0)
{
    constexpr int Kdim = DD, Ndim = DD;
    extern __shared__ char smem_raw[];
    const uint32_t sbase = cvta_s(smem_raw);

    const int z = blockIdx.z;
    const __nv_bfloat16* Bh = Bh0 + (size_t)z * DD * DD;
    const __nv_bfloat16* Bl = Bl0 + (size_t)z * DD * DD;
    __nv_bfloat16* Ch = (MODE == 1) ? Ch0 + (size_t)z * QSZ : nullptr;
    __nv_bfloat16* Cl = (MODE == 1) ? Cl0 + (size_t)z * QSZ : nullptr;

    const int tid  = threadIdx.x;
    const int wid  = tid >> 5, lane = tid & 31;
    const int wm   = wid & 1;
    const int wn   = wid >> 1;
    const int m0   = blockIdx.y * 128, n0 = blockIdx.x * 128;

    float acc[4][4][4] = {};

    auto load_chunk = [&](int c, int stage) {
        const uint32_t so = sbase + stage * STAGE_B;
        const int k0 = c * KCH;
        #pragma unroll
        for (int u = 0; u < 4; u++) {
            const int id  = tid + u * 256;
            const int row = id >> 3, cl = id & 7;
            const uint32_t sw = row * (TSTR * 2) + cl * 16;
            const size_t ga = (size_t)(m0 + row) * Kdim + k0 + cl * 8;
            const size_t gb = (size_t)(n0 + row) * Kdim + k0 + cl * 8;
            CP_ASYNC16(so + sw,              Ah + ga);
            CP_ASYNC16(so + TILE_B + sw,     Al + ga);
            CP_ASYNC16(so + 2 * TILE_B + sw, Bh + gb);
            CP_ASYNC16(so + 3 * TILE_B + sw, Bl + gb);
        }
        CP_ASYNC_COMMIT();
    };

    const uint32_t a_row = wm * 64 + (lane & 15);
    const uint32_t a_sub = (lane >> 4) * 16;
    const uint32_t b_row = wn * 32 + (lane & 7);
    const uint32_t b_sub = ((lane >> 3) & 1) * 16;

    auto compute = [&](int stage) {
        const uint32_t so = sbase + stage * STAGE_B;
        #pragma unroll
        for (int ks = 0; ks < 4; ks++) {
            uint32_t ah[4][4], al[4][4], bh[4][2], bl[4][2];
            #pragma unroll
            for (int i = 0; i < 4; i++) {
                const uint32_t off = (a_row + i * 16) * (TSTR * 2) + ks * 32 + a_sub;
                LDMATRIX_X4(ah[i][0], ah[i][1], ah[i][2], ah[i][3], so + off);
                LDMATRIX_X4(al[i][0], al[i][1], al[i][2], al[i][3], so + TILE_B + off);
            }
            #pragma unroll
            for (int j = 0; j < 4; j++) {
                const uint32_t off = (b_row + j * 8) * (TSTR * 2) + ks * 32 + b_sub;
                LDMATRIX_X2(bh[j][0], bh[j][1], so + 2 * TILE_B + off);
                LDMATRIX_X2(bl[j][0], bl[j][1], so + 3 * TILE_B + off);
            }
            #pragma unroll
            for (int i = 0; i < 4; i++)
                #pragma unroll
                for (int j = 0; j < 4; j++)
                    mma_bf16(acc[i][j], ah[i], bh[j][0], bh[j][1]);
            #pragma unroll
            for (int i = 0; i < 4; i++)
                #pragma unroll
                for (int j = 0; j < 4; j++)
                    mma_bf16(acc[i][j], ah[i], bl[j][0], bl[j][1]);
            #pragma unroll
            for (int i = 0; i < 4; i++)
                #pragma unroll
                for (int j = 0; j < 4; j++)
                    mma_bf16(acc[i][j], al[i], bh[j][0], bh[j][1]);
        }
    };

    const int NCHUNK = Kdim / KCH;       // 16
    load_chunk(0, 0);
    load_chunk(1, 1);
    #pragma unroll 1
    for (int c = 0; c < NCHUNK; c++) {
        if (c < NCHUNK - 1) { CP_ASYNC_WAIT(1); }
        else               { CP_ASYNC_WAIT(0); }
        __syncthreads();
        compute(c % 3);
        if (c + 2 < NCHUNK) load_chunk(c + 2, (c + 2) % 3);
    }

    #pragma unroll
    for (int i = 0; i < 4; i++) {
        #pragma unroll
        for (int j = 0; j < 4; j++) {
            const int col = n0 + wn * 32 + j * 8 + 2 * (lane & 3);
            #pragma unroll
            for (int hlf = 0; hlf < 2; hlf++) {
                const int row = m0 + wm * 64 + i * 16 + (lane >> 2) + hlf * 8;
                const float v0 = acc[i][j][hlf * 2], v1 = acc[i][j][hlf * 2 + 1];
                if (MODE == 0) {
                    float* p = C + (size_t)row * Ndim + col;
                    *(float2*)p = make_float2(v0, v1);
                } else {
                    const int b = row >> 10, s = row & 1023;
                    const int h = col >> 6, dk = col & 63;
                    const size_t off = ((size_t)(b * HH + h) * SS + s) * DKK + dk;
                    uint32_t hi, lo;
                    split2(v0, v1, hi, lo);
                    *(uint32_t*)(Ch + off) = hi;
                    *(uint32_t*)(Cl + off) = lo;
                }
            }
        }
    }
}

// ---------------------------------------------------------------------------
// Flash attention R14: BQ=256, 8 warps x 32 q-rows each (2 m16 blocks/warp).
// K/V fragments and bias/KV traffic amortized over 2x more MMAs per warp.
// Q fragments re-loaded from smem per tile (frees 64 permanent registers);
// QK loop is ks-outer so Q frags are 16 transient regs.
// 3-stage KV ring of 64-key tiles, 1 sync/tile. Emits O as bf16 hi/lo.
// ---------------------------------------------------------------------------
#define FBQ     256
#define FT_B    9216                      // 64x64 bf16 tile @ 144B rows
#define FSTG_B  (4 * FT_B)                // 36864
#define FQ_B    (256 * 144)               // 36864 (256-row Q tile)
#define FQH_OFF (3 * FSTG_B)              // 110592
#define FQL_OFF (FQH_OFF + FQ_B)          // 147456
#define FSMEM   (FQL_OFF + FQ_B)          // 184320

__global__ __launch_bounds__(256)
void flash_mma_kernel(const float* __restrict__ bias, const float* __restrict__ bt,
                      __nv_bfloat16* __restrict__ Oh, __nv_bfloat16* __restrict__ Ol)
{
    extern __shared__ char fsm[];
    const uint32_t sb = cvta_s(fsm);
    const int tid = threadIdx.x, wid = tid >> 5, lane = tid & 31;
    const int qb = blockIdx.x * FBQ, h = blockIdx.y, b = blockIdx.z;
    const int bh = b * HH + h;
    const float btv = bt[h];

    const __nv_bfloat16* Qhg = g_QKVh[0] + ((size_t)bh * SS + qb) * DKK;
    const __nv_bfloat16* Qlg = g_QKVl[0] + ((size_t)bh * SS + qb) * DKK;
    const __nv_bfloat16* Khg = g_QKVh[1] + (size_t)bh * SS * DKK;
    const __nv_bfloat16* Klg = g_QKVl[1] + (size_t)bh * SS * DKK;
    const __nv_bfloat16* Vhg = g_QKVh[2] + (size_t)bh * SS * DKK;
    const __nv_bfloat16* Vlg = g_QKVl[2] + (size_t)bh * SS * DKK;

    // Q load: 256 rows x 8 lines, hi+lo (own cp.async group)
    #pragma unroll
    for (int u = 0; u < 8; u++) {
        const int id = tid + u * 256;            // 0..2047
        const int row = id >> 3, c = id & 7;
        const uint32_t off = row * 144 + c * 16;
        CP_ASYNC16(sb + FQH_OFF + off, Qhg + row * 64 + c * 8);
        CP_ASYNC16(sb + FQL_OFF + off, Qlg + row * 64 + c * 8);
    }
    CP_ASYNC_COMMIT();

    auto load_kv = [&](int t, int stage) {
        const uint32_t so = sb + stage * FSTG_B;
        const size_t g0 = (size_t)(t * 64) * DKK;
        #pragma unroll
        for (int u = 0; u < 2; u++) {
            const int id = tid + u * 256;        // 0..511
            const int row = id >> 3, c = id & 7;
            const uint32_t off = row * 144 + c * 16;
            const size_t g = g0 + row * 64 + c * 8;
            CP_ASYNC16(so + off,            Khg + g);
            CP_ASYNC16(so + FT_B + off,     Klg + g);
            CP_ASYNC16(so + 2 * FT_B + off, Vhg + g);
            CP_ASYNC16(so + 3 * FT_B + off, Vlg + g);
        }
        CP_ASYNC_COMMIT();
    };

    load_kv(0, 0);
    load_kv(1, 1);
    CP_ASYNC_WAIT(2);       // Q group done
    __syncthreads();

    float out[2][8][4] = {};
    float mm[4] = {-CUDART_INF_F, -CUDART_INF_F, -CUDART_INF_F, -CUDART_INF_F};
    float ll[4] = {};

    const int rbase = qb + wid * 32;             // warp's first q-row (global)
    const int cb0 = 2 * (lane & 3);

    #pragma unroll 1
    for (int t = 0; t < 16; t++) {
        if (t < 15) { CP_ASYNC_WAIT(1); }
        else        { CP_ASYNC_WAIT(0); }
        __syncthreads();

        const uint32_t so = sb + (t % 3) * FSTG_B;

        // ---- S = Q K^T (ks-outer; Q frags transient) ----
        float sacc[2][8][4] = {};
        #pragma unroll
        for (int ks = 0; ks < 4; ks++) {
            uint32_t qh[2][4], ql[2][4];
            #pragma unroll
            for (int mb = 0; mb < 2; mb++) {
                const uint32_t qrow = wid * 32 + mb * 16 + (lane & 15);
                const uint32_t ad = sb + FQH_OFF + qrow * 144 + ks * 32 + (lane >> 4) * 16;
                LDMATRIX_X4(qh[mb][0], qh[mb][1], qh[mb][2], qh[mb][3], ad);
                LDMATRIX_X4(ql[mb][0], ql[mb][1], ql[mb][2], ql[mb][3], ad + FQ_B);
            }
            #pragma unroll
            for (int nb = 0; nb < 8; nb++) {
                uint32_t kh0, kh1, kl0, kl1;
                const uint32_t kad = so + (nb * 8 + (lane & 7)) * 144
                                   + ks * 32 + ((lane >> 3) & 1) * 16;
                LDMATRIX_X2(kh0, kh1, kad);
                LDMATRIX_X2(kl0, kl1, kad + FT_B);
                #pragma unroll
                for (int mb = 0; mb < 2; mb++) {
                    mma_bf16(sacc[mb][nb], qh[mb], kh0, kh1);
                    mma_bf16(sacc[mb][nb], qh[mb], kl0, kl1);
                    mma_bf16(sacc[mb][nb], ql[mb], kh0, kh1);
                }
            }
        }

        // ---- scale + bias, softmax per m-block ----
        uint32_t ph[2][8][2], pl[2][8][2];
        #pragma unroll
        for (int mb = 0; mb < 2; mb++) {
            const int i0 = mb * 2, i1 = mb * 2 + 1;
            const int r0 = rbase + mb * 16 + (lane >> 2);
            float tmax0 = mm[i0], tmax1 = mm[i1];
            #pragma unroll
            for (int nb = 0; nb < 8; nb++) {
                const int colg = t * 64 + nb * 8 + cb0;
                const float2 b0 = *(const float2*)(bias + (size_t)r0 * SS + colg);
                const float2 b1 = *(const float2*)(bias + (size_t)(r0 + 8) * SS + colg);
                sacc[mb][nb][0] = fmaf(btv, b0.x, sacc[mb][nb][0] * 0.125f);
                sacc[mb][nb][1] = fmaf(btv, b0.y, sacc[mb][nb][1] * 0.125f);
                sacc[mb][nb][2] = fmaf(btv, b1.x, sacc[mb][nb][2] * 0.125f);
                sacc[mb][nb][3] = fmaf(btv, b1.y, sacc[mb][nb][3] * 0.125f);
                tmax0 = fmaxf(tmax0, fmaxf(sacc[mb][nb][0], sacc[mb][nb][1]));
                tmax1 = fmaxf(tmax1, fmaxf(sacc[mb][nb][2], sacc[mb][nb][3]));
            }
            tmax0 = fmaxf(tmax0, __shfl_xor_sync(0xFFFFFFFF, tmax0, 1));
            tmax0 = fmaxf(tmax0, __shfl_xor_sync(0xFFFFFFFF, tmax0, 2));
            tmax1 = fmaxf(tmax1, __shfl_xor_sync(0xFFFFFFFF, tmax1, 1));
            tmax1 = fmaxf(tmax1, __shfl_xor_sync(0xFFFFFFFF, tmax1, 2));

            const float sc0 = __expf(mm[i0] - tmax0);
            const float sc1 = __expf(mm[i1] - tmax1);
            mm[i0] = tmax0; mm[i1] = tmax1;
            ll[i0] *= sc0;  ll[i1] *= sc1;
            #pragma unroll
            for (int nb = 0; nb < 8; nb++) {
                out[mb][nb][0] *= sc0; out[mb][nb][1] *= sc0;
                out[mb][nb][2] *= sc1; out[mb][nb][3] *= sc1;
            }

            float rs0 = 0.f, rs1 = 0.f;
            #pragma unroll
            for (int nb = 0; nb < 8; nb++) {
                const float p0 = __expf(sacc[mb][nb][0] - tmax0);
                const float p1 = __expf(sacc[mb][nb][1] - tmax0);
                const float p2 = __expf(sacc[mb][nb][2] - tmax1);
                const float p3 = __expf(sacc[mb][nb][3] - tmax1);
                rs0 += p0 + p1; rs1 += p2 + p3;
                split2(p0, p1, ph[mb][nb][0], pl[mb][nb][0]);
                split2(p2, p3, ph[mb][nb][1], pl[mb][nb][1]);
            }
            rs0 += __shfl_xor_sync(0xFFFFFFFF, rs0, 1);
            rs0 += __shfl_xor_sync(0xFFFFFFFF, rs0, 2);
            rs1 += __shfl_xor_sync(0xFFFFFFFF, rs1, 1);
            rs1 += __shfl_xor_sync(0xFFFFFFFF, rs1, 2);
            ll[i0] += rs0; ll[i1] += rs1;
        }

        // ---- out += P V (V frags shared across both m-blocks) ----
        #pragma unroll
        for (int nb = 0; nb < 8; nb++) {
            uint32_t vA[4], vB[4], wA[4], wB[4];
            const uint32_t vad = so + 2 * FT_B
                               + ((lane & 7) + 8 * (lane >> 3)) * 144 + nb * 16;
            LDMATRIX_X4T(vA[0], vA[1], vA[2], vA[3], vad);
            LDMATRIX_X4T(vB[0], vB[1], vB[2], vB[3], vad + 32 * 144);
            LDMATRIX_X4T(wA[0], wA[1], wA[2], wA[3], vad + FT_B);
            LDMATRIX_X4T(wB[0], wB[1], wB[2], wB[3], vad + FT_B + 32 * 144);
            #pragma unroll
            for (int ks = 0; ks < 4; ks++) {
                const uint32_t vh0 = (ks < 2) ? vA[2*ks]     : vB[2*(ks-2)];
                const uint32_t vh1 = (ks < 2) ? vA[2*ks + 1] : vB[2*(ks-2) + 1];
                const uint32_t vl0 = (ks < 2) ? wA[2*ks]     : wB[2*(ks-2)];
                const uint32_t vl1 = (ks < 2) ? wA[2*ks + 1] : wB[2*(ks-2) + 1];
                #pragma unroll
                for (int mb = 0; mb < 2; mb++) {
                    uint32_t aH[4] = { ph[mb][2*ks][0], ph[mb][2*ks][1],
                                       ph[mb][2*ks+1][0], ph[mb][2*ks+1][1] };
                    uint32_t aL[4] = { pl[mb][2*ks][0], pl[mb][2*ks][1],
                                       pl[mb][2*ks+1][0], pl[mb][2*ks+1][1] };
                    mma_bf16(out[mb][nb], aH, vh0, vh1);
                    mma_bf16(out[mb][nb], aH, vl0, vl1);
                    mma_bf16(out[mb][nb], aL, vh0, vh1);
                }
            }
        }

        if (t + 2 < 16) load_kv(t + 2, (t + 2) % 3);
    }

    // ---- normalize + store O as bf16 hi/lo, [B, S, H*DK] ----
    #pragma unroll
    for (int mb = 0; mb < 2; mb++) {
        const float inv0 = 1.f / ll[mb * 2];
        const float inv1 = 1.f / ll[mb * 2 + 1];
        const int r0 = rbase + mb * 16 + (lane >> 2);
        const size_t o0 = ((size_t)b * SS + r0) * (HH * DKK) + h * DKK;
        const size_t o1 = ((size_t)b * SS + r0 + 8) * (HH * DKK) + h * DKK;
        #pragma unroll
        for (int nb = 0; nb < 8; nb++) {
            const int dk = nb * 8 + cb0;
            uint32_t hi, lo;
            split2(out[mb][nb][0] * inv0, out[mb][nb][1] * inv0, hi, lo);
            *(uint32_t*)(Oh + o0 + dk) = hi;
            *(uint32_t*)(Ol + o0 + dk) = lo;
            split2(out[mb][nb][2] * inv1, out[mb][nb][3] * inv1, hi, lo);
            *(uint32_t*)(Oh + o1 + dk) = hi;
            *(uint32_t*)(Ol + o1 + dk) = lo;
        }
    }
}

// ---------------- launch ---------------------------------------------------
extern "C" void kernel_launch(void* const* d_in, const int* in_sizes, int n_in,
                              void* d_out, int out_size)
{
    (void)in_sizes; (void)n_in; (void)out_size;
    const float* X    = (const float*)d_in[0];
    const float* bias = (const float*)d_in[1];
    const float* Wmat[4] = { (const float*)d_in[2], (const float*)d_in[3],
                             (const float*)d_in[4], (const float*)d_in[5] };
    const float* bt = (const float*)d_in[6];
    float* out = (float*)d_out;

    __nv_bfloat16 *Ahp, *Alp, *Ohp, *Olp, *Whp, *Wlp, *QKVh, *QKVl;
    cudaGetSymbolAddress((void**)&Ahp,  g_Ah);
    cudaGetSymbolAddress((void**)&Alp,  g_Al);
    cudaGetSymbolAddress((void**)&Ohp,  g_Oh);
    cudaGetSymbolAddress((void**)&Olp,  g_Ol);
    cudaGetSymbolAddress((void**)&Whp,  g_Wh);
    cudaGetSymbolAddress((void**)&Wlp,  g_Wl);
    cudaGetSymbolAddress((void**)&QKVh, g_QKVh);
    cudaGetSymbolAddress((void**)&QKVl, g_QKVl);

    cudaFuncSetAttribute(mma_gemm_kernel<0>,
                         cudaFuncAttributeMaxDynamicSharedMemorySize, GSMEM);
    cudaFuncSetAttribute(mma_gemm_kernel<1>,
                         cudaFuncAttributeMaxDynamicSharedMemorySize, GSMEM);
    cudaFuncSetAttribute(flash_mma_kernel,
                         cudaFuncAttributeMaxDynamicSharedMemorySize, FSMEM);

    convert_hl_kernel<<<(MM * DD) / 1024, 256>>>(X, Ahp, Alp);
    for (int w = 0; w < 4; w++)
        convert_wt_kernel<<<dim3(32, 32), dim3(32, 8)>>>(
            Wmat[w], Whp + (size_t)w * DD * DD, Wlp + (size_t)w * DD * DD);

    dim3 qkv_grid(DD / 128, MM / 128, 3);
    mma_gemm_kernel<1><<<qkv_grid, 256, GSMEM>>>(Ahp, Alp, Whp, Wlp,
                                                 nullptr, QKVh, QKVl);

    flash_mma_kernel<<<dim3(SS / FBQ, HH, BB), 256, FSMEM>>>(bias, bt, Ohp, Olp);

    dim3 ogrid(DD / 128, MM / 128, 1);
    mma_gemm_kernel<0><<<ogrid, 256, GSMEM>>>(Ohp, Olp,
        Whp + 3 * (size_t)DD * DD, Wlp + 3 * (size_t)DD * DD, out, nullptr, nullptr);
}

// round 15
// speedup vs baseline: 1.2896x; 1.0139x over previous
#include <cuda_runtime.h>
#include <cuda_bf16.h>
#include <math_constants.h>
#include <cstdint>

#define BB  16
#define SS  1024
#define DD  1024
#define HH  16
#define DKK 64
#define MM  (BB*SS)          // 16384
#define QSZ (BB*HH*SS*DKK)   // 16M elems

// ---------------- scratch (__device__ globals; no runtime allocs) ----------
__device__ __nv_bfloat16 g_Ah[MM*DD];
__device__ __nv_bfloat16 g_Al[MM*DD];
__device__ __nv_bfloat16 g_Oh[MM*DD];
__device__ __nv_bfloat16 g_Ol[MM*DD];
__device__ __nv_bfloat16 g_Wh[4][DD*DD];
__device__ __nv_bfloat16 g_Wl[4][DD*DD];
__device__ __nv_bfloat16 g_QKVh[3][QSZ];
__device__ __nv_bfloat16 g_QKVl[3][QSZ];

// ---------------- PTX helpers (sm_80-era only) -----------------------------
__device__ __forceinline__ uint32_t cvta_s(const void* p) {
    return (uint32_t)__cvta_generic_to_shared(p);
}
#define CP_ASYNC16(saddr, gptr) \
    asm volatile("cp.async.cg.shared.global [%0], [%1], 16;" \
                 :: "r"((uint32_t)(saddr)), "l"(gptr))
#define CP_ASYNC_COMMIT() asm volatile("cp.async.commit_group;" ::: "memory")
#define CP_ASYNC_WAIT(n)  asm volatile("cp.async.wait_group %0;" :: "n"(n) : "memory")

#define LDMATRIX_X4(r0, r1, r2, r3, addr) \
    asm volatile("ldmatrix.sync.aligned.m8n8.x4.shared.b16 {%0,%1,%2,%3}, [%4];" \
                 : "=r"(r0), "=r"(r1), "=r"(r2), "=r"(r3) : "r"(addr))
#define LDMATRIX_X4T(r0, r1, r2, r3, addr) \
    asm volatile("ldmatrix.sync.aligned.m8n8.x4.trans.shared.b16 {%0,%1,%2,%3}, [%4];" \
                 : "=r"(r0), "=r"(r1), "=r"(r2), "=r"(r3) : "r"(addr))
#define LDMATRIX_X2(r0, r1, addr) \
    asm volatile("ldmatrix.sync.aligned.m8n8.x2.shared.b16 {%0,%1}, [%2];" \
                 : "=r"(r0), "=r"(r1) : "r"(addr))

__device__ __forceinline__ void mma_bf16(float* d, const uint32_t* a, uint32_t b0, uint32_t b1) {
    asm volatile("mma.sync.aligned.m16n8k16.row.col.f32.bf16.bf16.f32 "
        "{%0,%1,%2,%3}, {%4,%5,%6,%7}, {%8,%9}, {%0,%1,%2,%3};"
        : "+f"(d[0]), "+f"(d[1]), "+f"(d[2]), "+f"(d[3])
        : "r"(a[0]), "r"(a[1]), "r"(a[2]), "r"(a[3]), "r"(b0), "r"(b1));
}

__device__ __forceinline__ uint32_t pack2bf(float x, float y) {
    __nv_bfloat162 t = __floats2bfloat162_rn(x, y);
    return *reinterpret_cast<uint32_t*>(&t);
}
__device__ __forceinline__ void split2(float x, float y, uint32_t& hi, uint32_t& lo) {
    __nv_bfloat16 hx = __float2bfloat16(x), hy = __float2bfloat16(y);
    float rx = x - __bfloat162float(hx);
    float ry = y - __bfloat162float(hy);
    __nv_bfloat162 h2; h2.x = hx; h2.y = hy;
    hi = *reinterpret_cast<uint32_t*>(&h2);
    lo = pack2bf(rx, ry);
}

// ---------------- fp32 -> bf16 hi/lo split ---------------------------------
__global__ __launch_bounds__(256)
void convert_hl_kernel(const float* __restrict__ X,
                       __nv_bfloat16* __restrict__ H, __nv_bfloat16* __restrict__ L)
{
    const size_t i = ((size_t)blockIdx.x * 256 + threadIdx.x) * 4;
    float4 v = *(const float4*)(X + i);
    float f[4] = {v.x, v.y, v.z, v.w};
    ushort4 hv, lv;
    unsigned short* hp = &hv.x; unsigned short* lp = &lv.x;
    #pragma unroll
    for (int j = 0; j < 4; j++) {
        __nv_bfloat16 h = __float2bfloat16(f[j]);
        float r = f[j] - __bfloat162float(h);
        hp[j] = __bfloat16_as_ushort(h);
        lp[j] = __bfloat16_as_ushort(__float2bfloat16(r));
    }
    *(ushort4*)(H + i) = hv;
    *(ushort4*)(L + i) = lv;
}

// ---------------- W [K,N] -> W^T [N,K], split hi/lo ------------------------
__global__ __launch_bounds__(256)
void convert_wt_kernel(const float* __restrict__ W,
                       __nv_bfloat16* __restrict__ Th, __nv_bfloat16* __restrict__ Tl)
{
    __shared__ float tile[32][33];
    const int n0 = blockIdx.x * 32, k0 = blockIdx.y * 32;
    const int tx = threadIdx.x, ty = threadIdx.y;  // 32 x 8
    #pragma unroll
    for (int i = 0; i < 32; i += 8)
        tile[ty + i][tx] = W[(size_t)(k0 + ty + i) * DD + n0 + tx];
    __syncthreads();
    #pragma unroll
    for (int i = 0; i < 32; i += 8) {
        float v = tile[tx][ty + i];
        __nv_bfloat16 h = __float2bfloat16(v);
        float r = v - __bfloat162float(h);
        size_t o = (size_t)(n0 + ty + i) * DD + k0 + tx;
        Th[o] = h;
        Tl[o] = __float2bfloat16(r);
    }
}

// ---------------------------------------------------------------------------
// Tensor-core GEMM (R8 config) + R15: cp.async issuance for chunk c+2 is
// INTERLEAVED into compute(c)'s ks-steps (1/4 of the 4096 loads per step) so
// LDGSTS issue overlaps the MMA stream instead of serializing after it.
// Target stage (c+2)%3 == (c-1)%3, freed at the barrier just passed.
// ---------------------------------------------------------------------------
#define KCH    64
#define TSTR   72
#define TILE_B (128 * TSTR * 2)          // 18432
#define STAGE_B (4 * TILE_B)             // 73728
#define GSTAGES 3
#define GSMEM  (GSTAGES * STAGE_B)       // 221184

template<int MODE>
__global__ __launch_bounds__(256, 1)
void mma_gemm_kernel(const __nv_bfloat16* __restrict__ Ah, const __nv_bfloat16* __restrict__ Al,
                     const __nv_bfloat16* __restrict__ Bh0, const __nv_bfloat16* __restrict__ Bl0,
                     float* __restrict__ C,
                     __nv_bfloat16* __restrict__ Ch0, __nv_bfloat16* __restrict__ Cl0)
{
    constexpr int Kdim = DD, Ndim = DD;
    extern __shared__ char smem_raw[];
    const uint32_t sbase = cvta_s(smem_raw);

    const int z = blockIdx.z;
    const __nv_bfloat16* Bh = Bh0 + (size_t)z * DD * DD;
    const __nv_bfloat16* Bl = Bl0 + (size_t)z * DD * DD;
    __nv_bfloat16* Ch = (MODE == 1) ? Ch0 + (size_t)z * QSZ : nullptr;
    __nv_bfloat16* Cl = (MODE == 1) ? Cl0 + (size_t)z * QSZ : nullptr;

    const int tid  = threadIdx.x;
    const int wid  = tid >> 5, lane = tid & 31;
    const int wm   = wid & 1;
    const int wn   = wid >> 1;
    const int m0   = blockIdx.y * 128, n0 = blockIdx.x * 128;

    float acc[4][4][4] = {};

    auto load_chunk = [&](int c, int stage) {
        const uint32_t so = sbase + stage * STAGE_B;
        const int k0 = c * KCH;
        #pragma unroll
        for (int u = 0; u < 4; u++) {
            const int id  = tid + u * 256;
            const int row = id >> 3, cl = id & 7;
            const uint32_t sw = row * (TSTR * 2) + cl * 16;
            const size_t ga = (size_t)(m0 + row) * Kdim + k0 + cl * 8;
            const size_t gb = (size_t)(n0 + row) * Kdim + k0 + cl * 8;
            CP_ASYNC16(so + sw,              Ah + ga);
            CP_ASYNC16(so + TILE_B + sw,     Al + ga);
            CP_ASYNC16(so + 2 * TILE_B + sw, Bh + gb);
            CP_ASYNC16(so + 3 * TILE_B + sw, Bl + gb);
        }
        CP_ASYNC_COMMIT();
    };

    const uint32_t a_row = wm * 64 + (lane & 15);
    const uint32_t a_sub = (lane >> 4) * 16;
    const uint32_t b_row = wn * 32 + (lane & 7);
    const uint32_t b_sub = ((lane >> 3) & 1) * 16;

    // compute(c) with chunk cnext's loads interleaved per ks-step
    auto compute = [&](int stage, int cnext, int nstage, bool do_load) {
        const uint32_t so = sbase + stage * STAGE_B;
        const uint32_t sn = sbase + nstage * STAGE_B;
        const int k0n = cnext * KCH;
        #pragma unroll
        for (int ks = 0; ks < 4; ks++) {
            if (do_load) {                       // 1/4 of next chunk's lines
                const int id  = tid + ks * 256;
                const int row = id >> 3, cl = id & 7;
                const uint32_t sw = row * (TSTR * 2) + cl * 16;
                const size_t ga = (size_t)(m0 + row) * Kdim + k0n + cl * 8;
                const size_t gb = (size_t)(n0 + row) * Kdim + k0n + cl * 8;
                CP_ASYNC16(sn + sw,              Ah + ga);
                CP_ASYNC16(sn + TILE_B + sw,     Al + ga);
                CP_ASYNC16(sn + 2 * TILE_B + sw, Bh + gb);
                CP_ASYNC16(sn + 3 * TILE_B + sw, Bl + gb);
            }
            uint32_t ah[4][4], al[4][4], bh[4][2], bl[4][2];
            #pragma unroll
            for (int i = 0; i < 4; i++) {
                const uint32_t off = (a_row + i * 16) * (TSTR * 2) + ks * 32 + a_sub;
                LDMATRIX_X4(ah[i][0], ah[i][1], ah[i][2], ah[i][3], so + off);
                LDMATRIX_X4(al[i][0], al[i][1], al[i][2], al[i][3], so + TILE_B + off);
            }
            #pragma unroll
            for (int j = 0; j < 4; j++) {
                const uint32_t off = (b_row + j * 8) * (TSTR * 2) + ks * 32 + b_sub;
                LDMATRIX_X2(bh[j][0], bh[j][1], so + 2 * TILE_B + off);
                LDMATRIX_X2(bl[j][0], bl[j][1], so + 3 * TILE_B + off);
            }
            #pragma unroll
            for (int i = 0; i < 4; i++)
                #pragma unroll
                for (int j = 0; j < 4; j++)
                    mma_bf16(acc[i][j], ah[i], bh[j][0], bh[j][1]);
            #pragma unroll
            for (int i = 0; i < 4; i++)
                #pragma unroll
                for (int j = 0; j < 4; j++)
                    mma_bf16(acc[i][j], ah[i], bl[j][0], bl[j][1]);
            #pragma unroll
            for (int i = 0; i < 4; i++)
                #pragma unroll
                for (int j = 0; j < 4; j++)
                    mma_bf16(acc[i][j], al[i], bh[j][0], bh[j][1]);
        }
        if (do_load) CP_ASYNC_COMMIT();
    };

    const int NCHUNK = Kdim / KCH;       // 16
    load_chunk(0, 0);
    load_chunk(1, 1);
    #pragma unroll 1
    for (int c = 0; c < NCHUNK; c++) {
        if (c < NCHUNK - 1) { CP_ASYNC_WAIT(1); }
        else               { CP_ASYNC_WAIT(0); }
        __syncthreads();
        compute(c % 3, c + 2, (c + 2) % 3, c + 2 < NCHUNK);
    }

    #pragma unroll
    for (int i = 0; i < 4; i++) {
        #pragma unroll
        for (int j = 0; j < 4; j++) {
            const int col = n0 + wn * 32 + j * 8 + 2 * (lane & 3);
            #pragma unroll
            for (int hlf = 0; hlf < 2; hlf++) {
                const int row = m0 + wm * 64 + i * 16 + (lane >> 2) + hlf * 8;
                const float v0 = acc[i][j][hlf * 2], v1 = acc[i][j][hlf * 2 + 1];
                if (MODE == 0) {
                    float* p = C + (size_t)row * Ndim + col;
                    *(float2*)p = make_float2(v0, v1);
                } else {
                    const int b = row >> 10, s = row & 1023;
                    const int h = col >> 6, dk = col & 63;
                    const size_t off = ((size_t)(b * HH + h) * SS + s) * DKK + dk;
                    uint32_t hi, lo;
                    split2(v0, v1, hi, lo);
                    *(uint32_t*)(Ch + off) = hi;
                    *(uint32_t*)(Cl + off) = lo;
                }
            }
        }
    }
}

// ---------------------------------------------------------------------------
// Flash attention (R14 BQ=256 config) + R15: tile t+2's KV cp.asyncs are
// interleaved into the PV nb-loop (1/8 per nb step; tile select uniform).
// ---------------------------------------------------------------------------
#define FBQ     256
#define FT_B    9216                      // 64x64 bf16 tile @ 144B rows
#define FSTG_B  (4 * FT_B)                // 36864
#define FQ_B    (256 * 144)               // 36864 (256-row Q tile)
#define FQH_OFF (3 * FSTG_B)              // 110592
#define FQL_OFF (FQH_OFF + FQ_B)          // 147456
#define FSMEM   (FQL_OFF + FQ_B)          // 184320

__global__ __launch_bounds__(256)
void flash_mma_kernel(const float* __restrict__ bias, const float* __restrict__ bt,
                      __nv_bfloat16* __restrict__ Oh, __nv_bfloat16* __restrict__ Ol)
{
    extern __shared__ char fsm[];
    const uint32_t sb = cvta_s(fsm);
    const int tid = threadIdx.x, wid = tid >> 5, lane = tid & 31;
    const int qb = blockIdx.x * FBQ, h = blockIdx.y, b = blockIdx.z;
    const int bh = b * HH + h;
    const float btv = bt[h];

    const __nv_bfloat16* Qhg = g_QKVh[0] + ((size_t)bh * SS + qb) * DKK;
    const __nv_bfloat16* Qlg = g_QKVl[0] + ((size_t)bh * SS + qb) * DKK;
    const __nv_bfloat16* Khg = g_QKVh[1] + (size_t)bh * SS * DKK;
    const __nv_bfloat16* Klg = g_QKVl[1] + (size_t)bh * SS * DKK;
    const __nv_bfloat16* Vhg = g_QKVh[2] + (size_t)bh * SS * DKK;
    const __nv_bfloat16* Vlg = g_QKVl[2] + (size_t)bh * SS * DKK;
    const __nv_bfloat16* KVsrc[4] = { Khg, Klg, Vhg, Vlg };

    // Q load: 256 rows x 8 lines, hi+lo (own cp.async group)
    #pragma unroll
    for (int u = 0; u < 8; u++) {
        const int id = tid + u * 256;            // 0..2047
        const int row = id >> 3, c = id & 7;
        const uint32_t off = row * 144 + c * 16;
        CP_ASYNC16(sb + FQH_OFF + off, Qhg + row * 64 + c * 8);
        CP_ASYNC16(sb + FQL_OFF + off, Qlg + row * 64 + c * 8);
    }
    CP_ASYNC_COMMIT();

    auto load_kv = [&](int t, int stage) {
        const uint32_t so = sb + stage * FSTG_B;
        const size_t g0 = (size_t)(t * 64) * DKK;
        #pragma unroll
        for (int u = 0; u < 2; u++) {
            const int id = tid + u * 256;        // 0..511
            const int row = id >> 3, c = id & 7;
            const uint32_t off = row * 144 + c * 16;
            const size_t g = g0 + row * 64 + c * 8;
            CP_ASYNC16(so + off,            Khg + g);
            CP_ASYNC16(so + FT_B + off,     Klg + g);
            CP_ASYNC16(so + 2 * FT_B + off, Vhg + g);
            CP_ASYNC16(so + 3 * FT_B + off, Vlg + g);
        }
        CP_ASYNC_COMMIT();
    };

    load_kv(0, 0);
    load_kv(1, 1);
    CP_ASYNC_WAIT(2);       // Q group done
    __syncthreads();

    float out[2][8][4] = {};
    float mm[4] = {-CUDART_INF_F, -CUDART_INF_F, -CUDART_INF_F, -CUDART_INF_F};
    float ll[4] = {};

    const int rbase = qb + wid * 32;             // warp's first q-row (global)
    const int cb0 = 2 * (lane & 3);

    #pragma unroll 1
    for (int t = 0; t < 16; t++) {
        if (t < 15) { CP_ASYNC_WAIT(1); }
        else        { CP_ASYNC_WAIT(0); }
        __syncthreads();

        const uint32_t so = sb + (t % 3) * FSTG_B;
        const bool do_load = (t + 2 < 16);
        const uint32_t sn = sb + ((t + 2) % 3) * FSTG_B;
        const size_t g0n = (size_t)((t + 2) * 64) * DKK;

        // ---- S = Q K^T (ks-outer; Q frags transient) ----
        float sacc[2][8][4] = {};
        #pragma unroll
        for (int ks = 0; ks < 4; ks++) {
            uint32_t qh[2][4], ql[2][4];
            #pragma unroll
            for (int mb = 0; mb < 2; mb++) {
                const uint32_t qrow = wid * 32 + mb * 16 + (lane & 15);
                const uint32_t ad = sb + FQH_OFF + qrow * 144 + ks * 32 + (lane >> 4) * 16;
                LDMATRIX_X4(qh[mb][0], qh[mb][1], qh[mb][2], qh[mb][3], ad);
                LDMATRIX_X4(ql[mb][0], ql[mb][1], ql[mb][2], ql[mb][3], ad + FQ_B);
            }
            #pragma unroll
            for (int nb = 0; nb < 8; nb++) {
                uint32_t kh0, kh1, kl0, kl1;
                const uint32_t kad = so + (nb * 8 + (lane & 7)) * 144
                                   + ks * 32 + ((lane >> 3) & 1) * 16;
                LDMATRIX_X2(kh0, kh1, kad);
                LDMATRIX_X2(kl0, kl1, kad + FT_B);
                #pragma unroll
                for (int mb = 0; mb < 2; mb++) {
                    mma_bf16(sacc[mb][nb], qh[mb], kh0, kh1);
                    mma_bf16(sacc[mb][nb], qh[mb], kl0, kl1);
                    mma_bf16(sacc[mb][nb], ql[mb], kh0, kh1);
                }
            }
        }

        // ---- scale + bias, softmax per m-block ----
        uint32_t ph[2][8][2], pl[2][8][2];
        #pragma unroll
        for (int mb = 0; mb < 2; mb++) {
            const int i0 = mb * 2, i1 = mb * 2 + 1;
            const int r0 = rbase + mb * 16 + (lane >> 2);
            float tmax0 = mm[i0], tmax1 = mm[i1];
            #pragma unroll
            for (int nb = 0; nb < 8; nb++) {
                const int colg = t * 64 + nb * 8 + cb0;
                const float2 b0 = *(const float2*)(bias + (size_t)r0 * SS + colg);
                const float2 b1 = *(const float2*)(bias + (size_t)(r0 + 8) * SS + colg);
                sacc[mb][nb][0] = fmaf(btv, b0.x, sacc[mb][nb][0] * 0.125f);
                sacc[mb][nb][1] = fmaf(btv, b0.y, sacc[mb][nb][1] * 0.125f);
                sacc[mb][nb][2] = fmaf(btv, b1.x, sacc[mb][nb][2] * 0.125f);
                sacc[mb][nb][3] = fmaf(btv, b1.y, sacc[mb][nb][3] * 0.125f);
                tmax0 = fmaxf(tmax0, fmaxf(sacc[mb][nb][0], sacc[mb][nb][1]));
                tmax1 = fmaxf(tmax1, fmaxf(sacc[mb][nb][2], sacc[mb][nb][3]));
            }
            tmax0 = fmaxf(tmax0, __shfl_xor_sync(0xFFFFFFFF, tmax0, 1));
            tmax0 = fmaxf(tmax0, __shfl_xor_sync(0xFFFFFFFF, tmax0, 2));
            tmax1 = fmaxf(tmax1, __shfl_xor_sync(0xFFFFFFFF, tmax1, 1));
            tmax1 = fmaxf(tmax1, __shfl_xor_sync(0xFFFFFFFF, tmax1, 2));

            const float sc0 = __expf(mm[i0] - tmax0);
            const float sc1 = __expf(mm[i1] - tmax1);
            mm[i0] = tmax0; mm[i1] = tmax1;
            ll[i0] *= sc0;  ll[i1] *= sc1;
            #pragma unroll
            for (int nb = 0; nb < 8; nb++) {
                out[mb][nb][0] *= sc0; out[mb][nb][1] *= sc0;
                out[mb][nb][2] *= sc1; out[mb][nb][3] *= sc1;
            }

            float rs0 = 0.f, rs1 = 0.f;
            #pragma unroll
            for (int nb = 0; nb < 8; nb++) {
                const float p0 = __expf(sacc[mb][nb][0] - tmax0);
                const float p1 = __expf(sacc[mb][nb][1] - tmax0);
                const float p2 = __expf(sacc[mb][nb][2] - tmax1);
                const float p3 = __expf(sacc[mb][nb][3] - tmax1);
                rs0 += p0 + p1; rs1 += p2 + p3;
                split2(p0, p1, ph[mb][nb][0], pl[mb][nb][0]);
                split2(p2, p3, ph[mb][nb][1], pl[mb][nb][1]);
            }
            rs0 += __shfl_xor_sync(0xFFFFFFFF, rs0, 1);
            rs0 += __shfl_xor_sync(0xFFFFFFFF, rs0, 2);
            rs1 += __shfl_xor_sync(0xFFFFFFFF, rs1, 1);
            rs1 += __shfl_xor_sync(0xFFFFFFFF, rs1, 2);
            ll[i0] += rs0; ll[i1] += rs1;
        }

        // ---- out += P V, with tile t+2's KV loads interleaved per nb ----
        #pragma unroll
        for (int nb = 0; nb < 8; nb++) {
            if (do_load) {                       // 1/8 of next tile's 2048 lines
                const int tile = nb >> 1;        // uniform per nb step
                const int l = ((nb & 1) << 8) + tid;   // 0..511
                const int row = l >> 3, c = l & 7;
                const uint32_t off = row * 144 + c * 16;
                CP_ASYNC16(sn + tile * FT_B + off, KVsrc[tile] + g0n + row * 64 + c * 8);
            }
            uint32_t vA[4], vB[4], wA[4], wB[4];
            const uint32_t vad = so + 2 * FT_B
                               + ((lane & 7) + 8 * (lane >> 3)) * 144 + nb * 16;
            LDMATRIX_X4T(vA[0], vA[1], vA[2], vA[3], vad);
            LDMATRIX_X4T(vB[0], vB[1], vB[2], vB[3], vad + 32 * 144);
            LDMATRIX_X4T(wA[0], wA[1], wA[2], wA[3], vad + FT_B);
            LDMATRIX_X4T(wB[0], wB[1], wB[2], wB[3], vad + FT_B + 32 * 144);
            #pragma unroll
            for (int ks = 0; ks < 4; ks++) {
                const uint32_t vh0 = (ks < 2) ? vA[2*ks]     : vB[2*(ks-2)];
                const uint32_t vh1 = (ks < 2) ? vA[2*ks + 1] : vB[2*(ks-2) + 1];
                const uint32_t vl0 = (ks < 2) ? wA[2*ks]     : wB[2*(ks-2)];
                const uint32_t vl1 = (ks < 2) ? wA[2*ks + 1] : wB[2*(ks-2) + 1];
                #pragma unroll
                for (int mb = 0; mb < 2; mb++) {
                    uint32_t aH[4] = { ph[mb][2*ks][0], ph[mb][2*ks][1],
                                       ph[mb][2*ks+1][0], ph[mb][2*ks+1][1] };
                    uint32_t aL[4] = { pl[mb][2*ks][0], pl[mb][2*ks][1],
                                       pl[mb][2*ks+1][0], pl[mb][2*ks+1][1] };
                    mma_bf16(out[mb][nb], aH, vh0, vh1);
                    mma_bf16(out[mb][nb], aH, vl0, vl1);
                    mma_bf16(out[mb][nb], aL, vh0, vh1);
                }
            }
        }
        if (do_load) CP_ASYNC_COMMIT();
    }

    // ---- normalize + store O as bf16 hi/lo, [B, S, H*DK] ----
    #pragma unroll
    for (int mb = 0; mb < 2; mb++) {
        const float inv0 = 1.f / ll[mb * 2];
        const float inv1 = 1.f / ll[mb * 2 + 1];
        const int r0 = rbase + mb * 16 + (lane >> 2);
        const size_t o0 = ((size_t)b * SS + r0) * (HH * DKK) + h * DKK;
        const size_t o1 = ((size_t)b * SS + r0 + 8) * (HH * DKK) + h * DKK;
        #pragma unroll
        for (int nb = 0; nb < 8; nb++) {
            const int dk = nb * 8 + cb0;
            uint32_t hi, lo;
            split2(out[mb][nb][0] * inv0, out[mb][nb][1] * inv0, hi, lo);
            *(uint32_t*)(Oh + o0 + dk) = hi;
            *(uint32_t*)(Ol + o0 + dk) = lo;
            split2(out[mb][nb][2] * inv1, out[mb][nb][3] * inv1, hi, lo);
            *(uint32_t*)(Oh + o1 + dk) = hi;
            *(uint32_t*)(Ol + o1 + dk) = lo;
        }
    }
}

// ---------------- launch ---------------------------------------------------
extern "C" void kernel_launch(void* const* d_in, const int* in_sizes, int n_in,
                              void* d_out, int out_size)
{
    (void)in_sizes; (void)n_in; (void)out_size;
    const float* X    = (const float*)d_in[0];
    const float* bias = (const float*)d_in[1];
    const float* Wmat[4] = { (const float*)d_in[2], (const float*)d_in[3],
                             (const float*)d_in[4], (const float*)d_in[5] };
    const float* bt = (const float*)d_in[6];
    float* out = (float*)d_out;

    __nv_bfloat16 *Ahp, *Alp, *Ohp, *Olp, *Whp, *Wlp, *QKVh, *QKVl;
    cudaGetSymbolAddress((void**)&Ahp,  g_Ah);
    cudaGetSymbolAddress((void**)&Alp,  g_Al);
    cudaGetSymbolAddress((void**)&Ohp,  g_Oh);
    cudaGetSymbolAddress((void**)&Olp,  g_Ol);
    cudaGetSymbolAddress((void**)&Whp,  g_Wh);
    cudaGetSymbolAddress((void**)&Wlp,  g_Wl);
    cudaGetSymbolAddress((void**)&QKVh, g_QKVh);
    cudaGetSymbolAddress((void**)&QKVl, g_QKVl);

    cudaFuncSetAttribute(mma_gemm_kernel<0>,
                         cudaFuncAttributeMaxDynamicSharedMemorySize, GSMEM);
    cudaFuncSetAttribute(mma_gemm_kernel<1>,
                         cudaFuncAttributeMaxDynamicSharedMemorySize, GSMEM);
    cudaFuncSetAttribute(flash_mma_kernel,
                         cudaFuncAttributeMaxDynamicSharedMemorySize, FSMEM);

    convert_hl_kernel<<<(MM * DD) / 1024, 256>>>(X, Ahp, Alp);
    for (int w = 0; w < 4; w++)
        convert_wt_kernel<<<dim3(32, 32), dim3(32, 8)>>>(
            Wmat[w], Whp + (size_t)w * DD * DD, Wlp + (size_t)w * DD * DD);

    dim3 qkv_grid(DD / 128, MM / 128, 3);
    mma_gemm_kernel<1><<<qkv_grid, 256, GSMEM>>>(Ahp, Alp, Whp, Wlp,
                                                 nullptr, QKVh, QKVl);

    flash_mma_kernel<<<dim3(SS / FBQ, HH, BB), 256, FSMEM>>>(bias, bt, Ohp, Olp);

    dim3 ogrid(DD / 128, MM / 128, 1);
    mma_gemm_kernel<0><<<ogrid, 256, GSMEM>>>(Ohp, Olp,
        Whp + 3 * (size_t)DD * DD, Wlp + 3 * (size_t)DD * DD, out, nullptr, nullptr);
}

// round 16
// speedup vs baseline: 1.3091x; 1.0151x over previous
#include <cuda_runtime.h>
#include <cuda_bf16.h>
#include <math_constants.h>
#include <cstdint>

#define BB  16
#define SS  1024
#define DD  1024
#define HH  16
#define DKK 64
#define MM  (BB*SS)          // 16384
#define QSZ (BB*HH*SS*DKK)   // 16M elems

// ---------------- scratch (__device__ globals; no runtime allocs) ----------
__device__ __nv_bfloat16 g_Ah[MM*DD];
__device__ __nv_bfloat16 g_Al[MM*DD];
__device__ __nv_bfloat16 g_Oh[MM*DD];
__device__ __nv_bfloat16 g_Ol[MM*DD];
__device__ __nv_bfloat16 g_Wh[4][DD*DD];
__device__ __nv_bfloat16 g_Wl[4][DD*DD];
__device__ __nv_bfloat16 g_QKVh[3][QSZ];
__device__ __nv_bfloat16 g_QKVl[3][QSZ];

// ---------------- PTX helpers (sm_80-era only) -----------------------------
__device__ __forceinline__ uint32_t cvta_s(const void* p) {
    return (uint32_t)__cvta_generic_to_shared(p);
}
#define CP_ASYNC16(saddr, gptr) \
    asm volatile("cp.async.cg.shared.global [%0], [%1], 16;" \
                 :: "r"((uint32_t)(saddr)), "l"(gptr))
#define CP_ASYNC_COMMIT() asm volatile("cp.async.commit_group;" ::: "memory")
#define CP_ASYNC_WAIT(n)  asm volatile("cp.async.wait_group %0;" :: "n"(n) : "memory")

#define LDMATRIX_X4(r0, r1, r2, r3, addr) \
    asm volatile("ldmatrix.sync.aligned.m8n8.x4.shared.b16 {%0,%1,%2,%3}, [%4];" \
                 : "=r"(r0), "=r"(r1), "=r"(r2), "=r"(r3) : "r"(addr))
#define LDMATRIX_X4T(r0, r1, r2, r3, addr) \
    asm volatile("ldmatrix.sync.aligned.m8n8.x4.trans.shared.b16 {%0,%1,%2,%3}, [%4];" \
                 : "=r"(r0), "=r"(r1), "=r"(r2), "=r"(r3) : "r"(addr))
#define LDMATRIX_X2(r0, r1, addr) \
    asm volatile("ldmatrix.sync.aligned.m8n8.x2.shared.b16 {%0,%1}, [%2];" \
                 : "=r"(r0), "=r"(r1) : "r"(addr))

__device__ __forceinline__ void mma_bf16(float* d, const uint32_t* a, uint32_t b0, uint32_t b1) {
    asm volatile("mma.sync.aligned.m16n8k16.row.col.f32.bf16.bf16.f32 "
        "{%0,%1,%2,%3}, {%4,%5,%6,%7}, {%8,%9}, {%0,%1,%2,%3};"
        : "+f"(d[0]), "+f"(d[1]), "+f"(d[2]), "+f"(d[3])
        : "r"(a[0]), "r"(a[1]), "r"(a[2]), "r"(a[3]), "r"(b0), "r"(b1));
}

__device__ __forceinline__ uint32_t pack2bf(float x, float y) {
    __nv_bfloat162 t = __floats2bfloat162_rn(x, y);
    return *reinterpret_cast<uint32_t*>(&t);
}
__device__ __forceinline__ void split2(float x, float y, uint32_t& hi, uint32_t& lo) {
    __nv_bfloat16 hx = __float2bfloat16(x), hy = __float2bfloat16(y);
    float rx = x - __bfloat162float(hx);
    float ry = y - __bfloat162float(hy);
    __nv_bfloat162 h2; h2.x = hx; h2.y = hy;
    hi = *reinterpret_cast<uint32_t*>(&h2);
    lo = pack2bf(rx, ry);
}

// ---------------- fp32 -> bf16 hi/lo split ---------------------------------
__global__ __launch_bounds__(256)
void convert_hl_kernel(const float* __restrict__ X,
                       __nv_bfloat16* __restrict__ H, __nv_bfloat16* __restrict__ L)
{
    const size_t i = ((size_t)blockIdx.x * 256 + threadIdx.x) * 4;
    float4 v = *(const float4*)(X + i);
    float f[4] = {v.x, v.y, v.z, v.w};
    ushort4 hv, lv;
    unsigned short* hp = &hv.x; unsigned short* lp = &lv.x;
    #pragma unroll
    for (int j = 0; j < 4; j++) {
        __nv_bfloat16 h = __float2bfloat16(f[j]);
        float r = f[j] - __bfloat162float(h);
        hp[j] = __bfloat16_as_ushort(h);
        lp[j] = __bfloat16_as_ushort(__float2bfloat16(r));
    }
    *(ushort4*)(H + i) = hv;
    *(ushort4*)(L + i) = lv;
}

// ---------------- W [K,N] -> W^T [N,K], split hi/lo ------------------------
__global__ __launch_bounds__(256)
void convert_wt_kernel(const float* __restrict__ W,
                       __nv_bfloat16* __restrict__ Th, __nv_bfloat16* __restrict__ Tl)
{
    __shared__ float tile[32][33];
    const int n0 = blockIdx.x * 32, k0 = blockIdx.y * 32;
    const int tx = threadIdx.x, ty = threadIdx.y;  // 32 x 8
    #pragma unroll
    for (int i = 0; i < 32; i += 8)
        tile[ty + i][tx] = W[(size_t)(k0 + ty + i) * DD + n0 + tx];
    __syncthreads();
    #pragma unroll
    for (int i = 0; i < 32; i += 8) {
        float v = tile[tx][ty + i];
        __nv_bfloat16 h = __float2bfloat16(v);
        float r = v - __bfloat162float(h);
        size_t o = (size_t)(n0 + ty + i) * DD + k0 + tx;
        Th[o] = h;
        Tl[o] = __float2bfloat16(r);
    }
}

// ---------------------------------------------------------------------------
// Tensor-core GEMM (R15 structure) + R16: B fragments via X4-pair ldmatrix
// (one X4 covers two n8 blocks -> half the B fragment instructions).
// ---------------------------------------------------------------------------
#define KCH    64
#define TSTR   72
#define TILE_B (128 * TSTR * 2)          // 18432
#define STAGE_B (4 * TILE_B)             // 73728
#define GSTAGES 3
#define GSMEM  (GSTAGES * STAGE_B)       // 221184

template<int MODE>
__global__ __launch_bounds__(256, 1)
void mma_gemm_kernel(const __nv_bfloat16* __restrict__ Ah, const __nv_bfloat16* __restrict__ Al,
                     const __nv_bfloat16* __restrict__ Bh0, const __nv_bfloat16* __restrict__ Bl0,
                     float* __restrict__ C,
                     __nv_bfloat16* __restrict__ Ch0, __nv_bfloat16* __restrict__ Cl0)
{
    constexpr int Kdim = DD, Ndim = DD;
    extern __shared__ char smem_raw[];
    const uint32_t sbase = cvta_s(smem_raw);

    const int z = blockIdx.z;
    const __nv_bfloat16* Bh = Bh0 + (size_t)z * DD * DD;
    const __nv_bfloat16* Bl = Bl0 + (size_t)z * DD * DD;
    __nv_bfloat16* Ch = (MODE == 1) ? Ch0 + (size_t)z * QSZ : nullptr;
    __nv_bfloat16* Cl = (MODE == 1) ? Cl0 + (size_t)z * QSZ : nullptr;

    const int tid  = threadIdx.x;
    const int wid  = tid >> 5, lane = tid & 31;
    const int wm   = wid & 1;
    const int wn   = wid >> 1;
    const int m0   = blockIdx.y * 128, n0 = blockIdx.x * 128;

    float acc[4][4][4] = {};

    auto load_chunk = [&](int c, int stage) {
        const uint32_t so = sbase + stage * STAGE_B;
        const int k0 = c * KCH;
        #pragma unroll
        for (int u = 0; u < 4; u++) {
            const int id  = tid + u * 256;
            const int row = id >> 3, cl = id & 7;
            const uint32_t sw = row * (TSTR * 2) + cl * 16;
            const size_t ga = (size_t)(m0 + row) * Kdim + k0 + cl * 8;
            const size_t gb = (size_t)(n0 + row) * Kdim + k0 + cl * 8;
            CP_ASYNC16(so + sw,              Ah + ga);
            CP_ASYNC16(so + TILE_B + sw,     Al + ga);
            CP_ASYNC16(so + 2 * TILE_B + sw, Bh + gb);
            CP_ASYNC16(so + 3 * TILE_B + sw, Bl + gb);
        }
        CP_ASYNC_COMMIT();
    };

    const uint32_t a_row = wm * 64 + (lane & 15);
    const uint32_t a_sub = (lane >> 4) * 16;
    // X4-pair B addressing: lane group g = lane>>3 selects (j within pair, k-half)
    const int bg = lane >> 3;
    const uint32_t bp_row = wn * 32 + 8 * (bg >> 1) + (lane & 7);  // + p*16
    const uint32_t bp_sub = (bg & 1) * 16;

    auto compute = [&](int stage, int cnext, int nstage, bool do_load) {
        const uint32_t so = sbase + stage * STAGE_B;
        const uint32_t sn = sbase + nstage * STAGE_B;
        const int k0n = cnext * KCH;
        #pragma unroll
        for (int ks = 0; ks < 4; ks++) {
            if (do_load) {                       // 1/4 of next chunk's lines
                const int id  = tid + ks * 256;
                const int row = id >> 3, cl = id & 7;
                const uint32_t sw = row * (TSTR * 2) + cl * 16;
                const size_t ga = (size_t)(m0 + row) * Kdim + k0n + cl * 8;
                const size_t gb = (size_t)(n0 + row) * Kdim + k0n + cl * 8;
                CP_ASYNC16(sn + sw,              Ah + ga);
                CP_ASYNC16(sn + TILE_B + sw,     Al + ga);
                CP_ASYNC16(sn + 2 * TILE_B + sw, Bh + gb);
                CP_ASYNC16(sn + 3 * TILE_B + sw, Bl + gb);
            }
            uint32_t ah[4][4], al[4][4], bh[4][2], bl[4][2];
            #pragma unroll
            for (int i = 0; i < 4; i++) {
                const uint32_t off = (a_row + i * 16) * (TSTR * 2) + ks * 32 + a_sub;
                LDMATRIX_X4(ah[i][0], ah[i][1], ah[i][2], ah[i][3], so + off);
                LDMATRIX_X4(al[i][0], al[i][1], al[i][2], al[i][3], so + TILE_B + off);
            }
            #pragma unroll
            for (int p = 0; p < 2; p++) {        // pair of j blocks per X4
                const uint32_t off = (bp_row + p * 16) * (TSTR * 2) + ks * 32 + bp_sub;
                LDMATRIX_X4(bh[2*p][0], bh[2*p][1], bh[2*p+1][0], bh[2*p+1][1],
                            so + 2 * TILE_B + off);
                LDMATRIX_X4(bl[2*p][0], bl[2*p][1], bl[2*p+1][0], bl[2*p+1][1],
                            so + 3 * TILE_B + off);
            }
            #pragma unroll
            for (int i = 0; i < 4; i++)
                #pragma unroll
                for (int j = 0; j < 4; j++)
                    mma_bf16(acc[i][j], ah[i], bh[j][0], bh[j][1]);
            #pragma unroll
            for (int i = 0; i < 4; i++)
                #pragma unroll
                for (int j = 0; j < 4; j++)
                    mma_bf16(acc[i][j], ah[i], bl[j][0], bl[j][1]);
            #pragma unroll
            for (int i = 0; i < 4; i++)
                #pragma unroll
                for (int j = 0; j < 4; j++)
                    mma_bf16(acc[i][j], al[i], bh[j][0], bh[j][1]);
        }
        if (do_load) CP_ASYNC_COMMIT();
    };

    const int NCHUNK = Kdim / KCH;       // 16
    load_chunk(0, 0);
    load_chunk(1, 1);
    #pragma unroll 1
    for (int c = 0; c < NCHUNK; c++) {
        if (c < NCHUNK - 1) { CP_ASYNC_WAIT(1); }
        else               { CP_ASYNC_WAIT(0); }
        __syncthreads();
        compute(c % 3, c + 2, (c + 2) % 3, c + 2 < NCHUNK);
    }

    #pragma unroll
    for (int i = 0; i < 4; i++) {
        #pragma unroll
        for (int j = 0; j < 4; j++) {
            const int col = n0 + wn * 32 + j * 8 + 2 * (lane & 3);
            #pragma unroll
            for (int hlf = 0; hlf < 2; hlf++) {
                const int row = m0 + wm * 64 + i * 16 + (lane >> 2) + hlf * 8;
                const float v0 = acc[i][j][hlf * 2], v1 = acc[i][j][hlf * 2 + 1];
                if (MODE == 0) {
                    float* p = C + (size_t)row * Ndim + col;
                    *(float2*)p = make_float2(v0, v1);
                } else {
                    const int b = row >> 10, s = row & 1023;
                    const int h = col >> 6, dk = col & 63;
                    const size_t off = ((size_t)(b * HH + h) * SS + s) * DKK + dk;
                    uint32_t hi, lo;
                    split2(v0, v1, hi, lo);
                    *(uint32_t*)(Ch + off) = hi;
                    *(uint32_t*)(Cl + off) = lo;
                }
            }
        }
    }
}

// ---------------------------------------------------------------------------
// Flash attention (R15 structure) + R16: K fragments via X4-pair ldmatrix.
// ---------------------------------------------------------------------------
#define FBQ     256
#define FT_B    9216                      // 64x64 bf16 tile @ 144B rows
#define FSTG_B  (4 * FT_B)                // 36864
#define FQ_B    (256 * 144)               // 36864 (256-row Q tile)
#define FQH_OFF (3 * FSTG_B)              // 110592
#define FQL_OFF (FQH_OFF + FQ_B)          // 147456
#define FSMEM   (FQL_OFF + FQ_B)          // 184320

__global__ __launch_bounds__(256)
void flash_mma_kernel(const float* __restrict__ bias, const float* __restrict__ bt,
                      __nv_bfloat16* __restrict__ Oh, __nv_bfloat16* __restrict__ Ol)
{
    extern __shared__ char fsm[];
    const uint32_t sb = cvta_s(fsm);
    const int tid = threadIdx.x, wid = tid >> 5, lane = tid & 31;
    const int qb = blockIdx.x * FBQ, h = blockIdx.y, b = blockIdx.z;
    const int bh = b * HH + h;
    const float btv = bt[h];

    const __nv_bfloat16* Qhg = g_QKVh[0] + ((size_t)bh * SS + qb) * DKK;
    const __nv_bfloat16* Qlg = g_QKVl[0] + ((size_t)bh * SS + qb) * DKK;
    const __nv_bfloat16* Khg = g_QKVh[1] + (size_t)bh * SS * DKK;
    const __nv_bfloat16* Klg = g_QKVl[1] + (size_t)bh * SS * DKK;
    const __nv_bfloat16* Vhg = g_QKVh[2] + (size_t)bh * SS * DKK;
    const __nv_bfloat16* Vlg = g_QKVl[2] + (size_t)bh * SS * DKK;
    const __nv_bfloat16* KVsrc[4] = { Khg, Klg, Vhg, Vlg };

    // Q load: 256 rows x 8 lines, hi+lo (own cp.async group)
    #pragma unroll
    for (int u = 0; u < 8; u++) {
        const int id = tid + u * 256;            // 0..2047
        const int row = id >> 3, c = id & 7;
        const uint32_t off = row * 144 + c * 16;
        CP_ASYNC16(sb + FQH_OFF + off, Qhg + row * 64 + c * 8);
        CP_ASYNC16(sb + FQL_OFF + off, Qlg + row * 64 + c * 8);
    }
    CP_ASYNC_COMMIT();

    auto load_kv = [&](int t, int stage) {
        const uint32_t so = sb + stage * FSTG_B;
        const size_t g0 = (size_t)(t * 64) * DKK;
        #pragma unroll
        for (int u = 0; u < 2; u++) {
            const int id = tid + u * 256;        // 0..511
            const int row = id >> 3, c = id & 7;
            const uint32_t off = row * 144 + c * 16;
            const size_t g = g0 + row * 64 + c * 8;
            CP_ASYNC16(so + off,            Khg + g);
            CP_ASYNC16(so + FT_B + off,     Klg + g);
            CP_ASYNC16(so + 2 * FT_B + off, Vhg + g);
            CP_ASYNC16(so + 3 * FT_B + off, Vlg + g);
        }
        CP_ASYNC_COMMIT();
    };

    load_kv(0, 0);
    load_kv(1, 1);
    CP_ASYNC_WAIT(2);       // Q group done
    __syncthreads();

    float out[2][8][4] = {};
    float mm[4] = {-CUDART_INF_F, -CUDART_INF_F, -CUDART_INF_F, -CUDART_INF_F};
    float ll[4] = {};

    const int rbase = qb + wid * 32;
    const int cb0 = 2 * (lane & 3);
    // X4-pair K addressing
    const int kg = lane >> 3;
    const uint32_t kp_row = 8 * (kg >> 1) + (lane & 7);   // + np*16
    const uint32_t kp_sub = (kg & 1) * 16;

    #pragma unroll 1
    for (int t = 0; t < 16; t++) {
        if (t < 15) { CP_ASYNC_WAIT(1); }
        else        { CP_ASYNC_WAIT(0); }
        __syncthreads();

        const uint32_t so = sb + (t % 3) * FSTG_B;
        const bool do_load = (t + 2 < 16);
        const uint32_t sn = sb + ((t + 2) % 3) * FSTG_B;
        const size_t g0n = (size_t)((t + 2) * 64) * DKK;

        // ---- S = Q K^T (ks-outer; Q frags transient; K via X4-pair) ----
        float sacc[2][8][4] = {};
        #pragma unroll
        for (int ks = 0; ks < 4; ks++) {
            uint32_t qh[2][4], ql[2][4];
            #pragma unroll
            for (int mb = 0; mb < 2; mb++) {
                const uint32_t qrow = wid * 32 + mb * 16 + (lane & 15);
                const uint32_t ad = sb + FQH_OFF + qrow * 144 + ks * 32 + (lane >> 4) * 16;
                LDMATRIX_X4(qh[mb][0], qh[mb][1], qh[mb][2], qh[mb][3], ad);
                LDMATRIX_X4(ql[mb][0], ql[mb][1], ql[mb][2], ql[mb][3], ad + FQ_B);
            }
            #pragma unroll
            for (int np = 0; np < 4; np++) {     // pair of nb blocks per X4
                uint32_t kh[4], kl[4];
                const uint32_t kad = so + (np * 16 + kp_row) * 144 + ks * 32 + kp_sub;
                LDMATRIX_X4(kh[0], kh[1], kh[2], kh[3], kad);
                LDMATRIX_X4(kl[0], kl[1], kl[2], kl[3], kad + FT_B);
                #pragma unroll
                for (int mb = 0; mb < 2; mb++) {
                    mma_bf16(sacc[mb][2*np],   qh[mb], kh[0], kh[1]);
                    mma_bf16(sacc[mb][2*np+1], qh[mb], kh[2], kh[3]);
                    mma_bf16(sacc[mb][2*np],   qh[mb], kl[0], kl[1]);
                    mma_bf16(sacc[mb][2*np+1], qh[mb], kl[2], kl[3]);
                    mma_bf16(sacc[mb][2*np],   ql[mb], kh[0], kh[1]);
                    mma_bf16(sacc[mb][2*np+1], ql[mb], kh[2], kh[3]);
                }
            }
        }

        // ---- scale + bias, softmax per m-block ----
        uint32_t ph[2][8][2], pl[2][8][2];
        #pragma unroll
        for (int mb = 0; mb < 2; mb++) {
            const int i0 = mb * 2, i1 = mb * 2 + 1;
            const int r0 = rbase + mb * 16 + (lane >> 2);
            float tmax0 = mm[i0], tmax1 = mm[i1];
            #pragma unroll
            for (int nb = 0; nb < 8; nb++) {
                const int colg = t * 64 + nb * 8 + cb0;
                const float2 b0 = *(const float2*)(bias + (size_t)r0 * SS + colg);
                const float2 b1 = *(const float2*)(bias + (size_t)(r0 + 8) * SS + colg);
                sacc[mb][nb][0] = fmaf(btv, b0.x, sacc[mb][nb][0] * 0.125f);
                sacc[mb][nb][1] = fmaf(btv, b0.y, sacc[mb][nb][1] * 0.125f);
                sacc[mb][nb][2] = fmaf(btv, b1.x, sacc[mb][nb][2] * 0.125f);
                sacc[mb][nb][3] = fmaf(btv, b1.y, sacc[mb][nb][3] * 0.125f);
                tmax0 = fmaxf(tmax0, fmaxf(sacc[mb][nb][0], sacc[mb][nb][1]));
                tmax1 = fmaxf(tmax1, fmaxf(sacc[mb][nb][2], sacc[mb][nb][3]));
            }
            tmax0 = fmaxf(tmax0, __shfl_xor_sync(0xFFFFFFFF, tmax0, 1));
            tmax0 = fmaxf(tmax0, __shfl_xor_sync(0xFFFFFFFF, tmax0, 2));
            tmax1 = fmaxf(tmax1, __shfl_xor_sync(0xFFFFFFFF, tmax1, 1));
            tmax1 = fmaxf(tmax1, __shfl_xor_sync(0xFFFFFFFF, tmax1, 2));

            const float sc0 = __expf(mm[i0] - tmax0);
            const float sc1 = __expf(mm[i1] - tmax1);
            mm[i0] = tmax0; mm[i1] = tmax1;
            ll[i0] *= sc0;  ll[i1] *= sc1;
            #pragma unroll
            for (int nb = 0; nb < 8; nb++) {
                out[mb][nb][0] *= sc0; out[mb][nb][1] *= sc0;
                out[mb][nb][2] *= sc1; out[mb][nb][3] *= sc1;
            }

            float rs0 = 0.f, rs1 = 0.f;
            #pragma unroll
            for (int nb = 0; nb < 8; nb++) {
                const float p0 = __expf(sacc[mb][nb][0] - tmax0);
                const float p1 = __expf(sacc[mb][nb][1] - tmax0);
                const float p2 = __expf(sacc[mb][nb][2] - tmax1);
                const float p3 = __expf(sacc[mb][nb][3] - tmax1);
                rs0 += p0 + p1; rs1 += p2 + p3;
                split2(p0, p1, ph[mb][nb][0], pl[mb][nb][0]);
                split2(p2, p3, ph[mb][nb][1], pl[mb][nb][1]);
            }
            rs0 += __shfl_xor_sync(0xFFFFFFFF, rs0, 1);
            rs0 += __shfl_xor_sync(0xFFFFFFFF, rs0, 2);
            rs1 += __shfl_xor_sync(0xFFFFFFFF, rs1, 1);
            rs1 += __shfl_xor_sync(0xFFFFFFFF, rs1, 2);
            ll[i0] += rs0; ll[i1] += rs1;
        }

        // ---- out += P V, with tile t+2's KV loads interleaved per nb ----
        #pragma unroll
        for (int nb = 0; nb < 8; nb++) {
            if (do_load) {                       // 1/8 of next tile's 2048 lines
                const int tile = nb >> 1;
                const int l = ((nb & 1) << 8) + tid;   // 0..511
                const int row = l >> 3, c = l & 7;
                const uint32_t off = row * 144 + c * 16;
                CP_ASYNC16(sn + tile * FT_B + off, KVsrc[tile] + g0n + row * 64 + c * 8);
            }
            uint32_t vA[4], vB[4], wA[4], wB[4];
            const uint32_t vad = so + 2 * FT_B
                               + ((lane & 7) + 8 * (lane >> 3)) * 144 + nb * 16;
            LDMATRIX_X4T(vA[0], vA[1], vA[2], vA[3], vad);
            LDMATRIX_X4T(vB[0], vB[1], vB[2], vB[3], vad + 32 * 144);
            LDMATRIX_X4T(wA[0], wA[1], wA[2], wA[3], vad + FT_B);
            LDMATRIX_X4T(wB[0], wB[1], wB[2], wB[3], vad + FT_B + 32 * 144);
            #pragma unroll
            for (int ks = 0; ks < 4; ks++) {
                const uint32_t vh0 = (ks < 2) ? vA[2*ks]     : vB[2*(ks-2)];
                const uint32_t vh1 = (ks < 2) ? vA[2*ks + 1] : vB[2*(ks-2) + 1];
                const uint32_t vl0 = (ks < 2) ? wA[2*ks]     : wB[2*(ks-2)];
                const uint32_t vl1 = (ks < 2) ? wA[2*ks + 1] : wB[2*(ks-2) + 1];
                #pragma unroll
                for (int mb = 0; mb < 2; mb++) {
                    uint32_t aH[4] = { ph[mb][2*ks][0], ph[mb][2*ks][1],
                                       ph[mb][2*ks+1][0], ph[mb][2*ks+1][1] };
                    uint32_t aL[4] = { pl[mb][2*ks][0], pl[mb][2*ks][1],
                                       pl[mb][2*ks+1][0], pl[mb][2*ks+1][1] };
                    mma_bf16(out[mb][nb], aH, vh0, vh1);
                    mma_bf16(out[mb][nb], aH, vl0, vl1);
                    mma_bf16(out[mb][nb], aL, vh0, vh1);
                }
            }
        }
        if (do_load) CP_ASYNC_COMMIT();
    }

    // ---- normalize + store O as bf16 hi/lo, [B, S, H*DK] ----
    #pragma unroll
    for (int mb = 0; mb < 2; mb++) {
        const float inv0 = 1.f / ll[mb * 2];
        const float inv1 = 1.f / ll[mb * 2 + 1];
        const int r0 = rbase + mb * 16 + (lane >> 2);
        const size_t o0 = ((size_t)b * SS + r0) * (HH * DKK) + h * DKK;
        const size_t o1 = ((size_t)b * SS + r0 + 8) * (HH * DKK) + h * DKK;
        #pragma unroll
        for (int nb = 0; nb < 8; nb++) {
            const int dk = nb * 8 + cb0;
            uint32_t hi, lo;
            split2(out[mb][nb][0] * inv0, out[mb][nb][1] * inv0, hi, lo);
            *(uint32_t*)(Oh + o0 + dk) = hi;
            *(uint32_t*)(Ol + o0 + dk) = lo;
            split2(out[mb][nb][2] * inv1, out[mb][nb][3] * inv1, hi, lo);
            *(uint32_t*)(Oh + o1 + dk) = hi;
            *(uint32_t*)(Ol + o1 + dk) = lo;
        }
    }
}

// ---------------- launch ---------------------------------------------------
extern "C" void kernel_launch(void* const* d_in, const int* in_sizes, int n_in,
                              void* d_out, int out_size)
{
    (void)in_sizes; (void)n_in; (void)out_size;
    const float* X    = (const float*)d_in[0];
    const float* bias = (const float*)d_in[1];
    const float* Wmat[4] = { (const float*)d_in[2], (const float*)d_in[3],
                             (const float*)d_in[4], (const float*)d_in[5] };
    const float* bt = (const float*)d_in[6];
    float* out = (float*)d_out;

    __nv_bfloat16 *Ahp, *Alp, *Ohp, *Olp, *Whp, *Wlp, *QKVh, *QKVl;
    cudaGetSymbolAddress((void**)&Ahp,  g_Ah);
    cudaGetSymbolAddress((void**)&Alp,  g_Al);
    cudaGetSymbolAddress((void**)&Ohp,  g_Oh);
    cudaGetSymbolAddress((void**)&Olp,  g_Ol);
    cudaGetSymbolAddress((void**)&Whp,  g_Wh);
    cudaGetSymbolAddress((void**)&Wlp,  g_Wl);
    cudaGetSymbolAddress((void**)&QKVh, g_QKVh);
    cudaGetSymbolAddress((void**)&QKVl, g_QKVl);

    cudaFuncSetAttribute(mma_gemm_kernel<0>,
                         cudaFuncAttributeMaxDynamicSharedMemorySize, GSMEM);
    cudaFuncSetAttribute(mma_gemm_kernel<1>,
                         cudaFuncAttributeMaxDynamicSharedMemorySize, GSMEM);
    cudaFuncSetAttribute(flash_mma_kernel,
                         cudaFuncAttributeMaxDynamicSharedMemorySize, FSMEM);

    convert_hl_kernel<<<(MM * DD) / 1024, 256>>>(X, Ahp, Alp);
    for (int w = 0; w < 4; w++)
        convert_wt_kernel<<<dim3(32, 32), dim3(32, 8)>>>(
            Wmat[w], Whp + (size_t)w * DD * DD, Wlp + (size_t)w * DD * DD);

    dim3 qkv_grid(DD / 128, MM / 128, 3);
    mma_gemm_kernel<1><<<qkv_grid, 256, GSMEM>>>(Ahp, Alp, Whp, Wlp,
                                                 nullptr, QKVh, QKVl);

    flash_mma_kernel<<<dim3(SS / FBQ, HH, BB), 256, FSMEM>>>(bias, bt, Ohp, Olp);

    dim3 ogrid(DD / 128, MM / 128, 1);
    mma_gemm_kernel<0><<<ogrid, 256, GSMEM>>>(Ohp, Olp,
        Whp + 3 * (size_t)DD * DD, Wlp + 3 * (size_t)DD * DD, out, nullptr, nullptr);
}